// round 1
// baseline (speedup 1.0000x reference)
#include <cuda_runtime.h>

#define NTOK   49
#define NHEADS 8
#define HDIM   32
#define CDIM   256
#define BWIN   4096
#define MROWS  (BWIN * NTOK)   /* 200704 */
#define NWIN   64

// Scratch (device-global arrays: allocation-free per harness rules)
__device__ float g_qkv[(size_t)MROWS * 3 * CDIM];   // (M, 768): col j = s*256 + h*32 + d
__device__ float g_att[(size_t)MROWS * CDIM];       // (M, 256): col = h*32 + d

__device__ __forceinline__ unsigned f2tf(float x) {
    unsigned u;
    asm("cvt.rna.tf32.f32 %0, %1;" : "=r"(u) : "f"(x));
    return u;
}

__device__ __forceinline__ void mma8(float* c, const unsigned* a, const unsigned* b) {
    asm volatile(
        "mma.sync.aligned.m16n8k8.row.col.f32.tf32.tf32.f32 "
        "{%0,%1,%2,%3}, {%4,%5,%6,%7}, {%8,%9}, {%0,%1,%2,%3};\n"
        : "+f"(c[0]), "+f"(c[1]), "+f"(c[2]), "+f"(c[3])
        : "r"(a[0]), "r"(a[1]), "r"(a[2]), "r"(a[3]), "r"(b[0]), "r"(b[1]));
}

// ---------------------------------------------------------------------------
// C[M,N] = A[M,K] @ B[N,K]^T + bias[N]   (all fp32 in gmem, tf32 mma compute)
// M % 128 == 0, N % 128 == 0, K % 16 == 0 (true for both call sites)
// grid = (N/128, M/128), blockIdx.x fastest -> A tile reused across N tiles in L2
// ---------------------------------------------------------------------------
#define BM 128
#define BN 128
#define BK 16
#define KST 20   /* smem row stride: (20r+c)%32 conflict-free for frag loads */

__global__ __launch_bounds__(256, 2)
void gemm_tf32_bias(const float* __restrict__ A, const float* __restrict__ B,
                    const float* __restrict__ bias, float* __restrict__ C,
                    int N, int K)
{
    __shared__ unsigned As[BM * KST];
    __shared__ unsigned Bs[BN * KST];

    const int tid   = threadIdx.x;
    const int lane  = tid & 31;
    const int wid   = tid >> 5;
    const int g     = lane >> 2;   // group id 0..7
    const int tg    = lane & 3;    // thread-in-group 0..3
    const int warpM = wid & 1;     // 2 warps along M (64 rows each)
    const int warpN = wid >> 1;    // 4 warps along N (32 cols each)

    const float* Ab = A + (size_t)blockIdx.y * BM * K;
    const float* Bb = B + (size_t)blockIdx.x * BN * K;

    // gmem->smem: 512 float4 per tile, 2 per thread
    const int ldrow = tid >> 2;        // 0..63
    const int ldc4  = (tid & 3) << 2;  // 0,4,8,12

    float4 ra[2], rb[2];
#pragma unroll
    for (int i = 0; i < 2; i++) {
        ra[i] = *(const float4*)(Ab + (size_t)(ldrow + i * 64) * K + ldc4);
        rb[i] = *(const float4*)(Bb + (size_t)(ldrow + i * 64) * K + ldc4);
    }
#pragma unroll
    for (int i = 0; i < 2; i++) {
        const int r = ldrow + i * 64;
        uint4 ua = make_uint4(f2tf(ra[i].x), f2tf(ra[i].y), f2tf(ra[i].z), f2tf(ra[i].w));
        *(uint4*)&As[r * KST + ldc4] = ua;
        uint4 ub = make_uint4(f2tf(rb[i].x), f2tf(rb[i].y), f2tf(rb[i].z), f2tf(rb[i].w));
        *(uint4*)&Bs[r * KST + ldc4] = ub;
    }
    __syncthreads();

    float acc[4][4][4];
#pragma unroll
    for (int mt = 0; mt < 4; mt++)
#pragma unroll
        for (int nt = 0; nt < 4; nt++)
#pragma unroll
            for (int i = 0; i < 4; i++) acc[mt][nt][i] = 0.f;

    const int KT = K / BK;
    for (int kt = 0; kt < KT; kt++) {
        if (kt + 1 < KT) {
#pragma unroll
            for (int i = 0; i < 2; i++) {
                ra[i] = *(const float4*)(Ab + (size_t)(ldrow + i * 64) * K + (kt + 1) * BK + ldc4);
                rb[i] = *(const float4*)(Bb + (size_t)(ldrow + i * 64) * K + (kt + 1) * BK + ldc4);
            }
        }
#pragma unroll
        for (int k8 = 0; k8 < 2; k8++) {
            unsigned af[4][4], bf[4][2];
#pragma unroll
            for (int mt = 0; mt < 4; mt++) {
                const int base = (warpM * 64 + mt * 16 + g) * KST + k8 * 8 + tg;
                af[mt][0] = As[base];
                af[mt][1] = As[base + 8 * KST];
                af[mt][2] = As[base + 4];
                af[mt][3] = As[base + 8 * KST + 4];
            }
#pragma unroll
            for (int nt = 0; nt < 4; nt++) {
                const int base = (warpN * 32 + nt * 8 + g) * KST + k8 * 8 + tg;
                bf[nt][0] = Bs[base];
                bf[nt][1] = Bs[base + 4];
            }
#pragma unroll
            for (int mt = 0; mt < 4; mt++)
#pragma unroll
                for (int nt = 0; nt < 4; nt++)
                    mma8(acc[mt][nt], af[mt], bf[nt]);
        }
        __syncthreads();
        if (kt + 1 < KT) {
#pragma unroll
            for (int i = 0; i < 2; i++) {
                const int r = ldrow + i * 64;
                uint4 ua = make_uint4(f2tf(ra[i].x), f2tf(ra[i].y), f2tf(ra[i].z), f2tf(ra[i].w));
                *(uint4*)&As[r * KST + ldc4] = ua;
                uint4 ub = make_uint4(f2tf(rb[i].x), f2tf(rb[i].y), f2tf(rb[i].z), f2tf(rb[i].w));
                *(uint4*)&Bs[r * KST + ldc4] = ub;
            }
        }
        __syncthreads();
    }

    // epilogue: c0 (g, 2tg), c1 (g, 2tg+1), c2/c3 at row+8
#pragma unroll
    for (int mt = 0; mt < 4; mt++) {
        const int r = blockIdx.y * BM + warpM * 64 + mt * 16 + g;
#pragma unroll
        for (int nt = 0; nt < 4; nt++) {
            const int c = blockIdx.x * BN + warpN * 32 + nt * 8 + tg * 2;
            const float2 bb = *(const float2*)(bias + c);
            float2 lo = make_float2(acc[mt][nt][0] + bb.x, acc[mt][nt][1] + bb.y);
            float2 hi = make_float2(acc[mt][nt][2] + bb.x, acc[mt][nt][3] + bb.y);
            *(float2*)(C + (size_t)r * N + c)       = lo;
            *(float2*)(C + (size_t)(r + 8) * N + c) = hi;
        }
    }
}

// ---------------------------------------------------------------------------
// Window attention: one block per (window b, head h). fp32 in smem.
// ---------------------------------------------------------------------------
#define QST 36   /* q/k/v smem row stride (floats) */
#define AST 50   /* attn smem row stride */

__global__ __launch_bounds__(128)
void win_attn(const float* __restrict__ qkv, const float* __restrict__ mask,
              const float* __restrict__ rpb, float* __restrict__ out)
{
    const int b = blockIdx.x >> 3;
    const int h = blockIdx.x & 7;
    const int tid  = threadIdx.x;
    const int lane = tid & 31;
    const int wid  = tid >> 5;

    // padded to 52 rows so unguarded tile reads stay in-bounds
    __shared__ float sq[52 * QST];
    __shared__ float sk[52 * QST];
    __shared__ float sv[52 * QST];
    __shared__ float sa[52 * AST];

    const float scale = 0.17677669529663687f;  // 32^-0.5
    const size_t rowbase = (size_t)b * NTOK * (3 * CDIM);
    const int hoff = h * HDIM;

    // Phase 1a: load q (pre-scaled), k, v
    for (int idx = tid; idx < NTOK * HDIM; idx += 128) {
        const int n = idx >> 5, d = idx & 31;
        const float* p = qkv + rowbase + (size_t)n * (3 * CDIM) + hoff + d;
        sq[n * QST + d] = p[0] * scale;
        sk[n * QST + d] = p[CDIM];
        sv[n * QST + d] = p[2 * CDIM];
    }
    // Phase 1b: preload mask + relative-position bias into the attn tile
    const float* mrow = mask + (size_t)(b & (NWIN - 1)) * (NTOK * NTOK);
    for (int idx = tid; idx < NTOK * NTOK; idx += 128) {
        const int n = idx / 49, m = idx - n * 49;
        const int r1 = n / 7, c1 = n - r1 * 7;
        const int r2 = m / 7, c2 = m - r2 * 7;
        const int bi = (r1 - r2 + 6) * 13 + (c1 - c2 + 6);
        sa[n * AST + m] = mrow[idx] + rpb[bi * NHEADS + h];
    }
    __syncthreads();

    // Phase 2: attn += Q @ K^T, 13x13 grid of 4x4 register tiles
    for (int t = tid; t < 169; t += 128) {
        const int n0 = (t / 13) * 4;
        const int m0 = (t % 13) * 4;
        float acc[4][4];
#pragma unroll
        for (int i = 0; i < 4; i++)
#pragma unroll
            for (int j = 0; j < 4; j++) acc[i][j] = 0.f;
#pragma unroll
        for (int d4 = 0; d4 < 8; d4++) {
            float4 qv[4], kv[4];
#pragma unroll
            for (int i = 0; i < 4; i++) {
                qv[i] = *(const float4*)&sq[(n0 + i) * QST + d4 * 4];
                kv[i] = *(const float4*)&sk[(m0 + i) * QST + d4 * 4];
            }
#pragma unroll
            for (int i = 0; i < 4; i++)
#pragma unroll
                for (int j = 0; j < 4; j++)
                    acc[i][j] += qv[i].x * kv[j].x + qv[i].y * kv[j].y
                               + qv[i].z * kv[j].z + qv[i].w * kv[j].w;
        }
#pragma unroll
        for (int i = 0; i < 4; i++) {
            const int n = n0 + i;
            if (n < 49) {
#pragma unroll
                for (int j = 0; j < 4; j++) {
                    const int m = m0 + j;
                    if (m < 49) sa[n * AST + m] += acc[i][j];
                }
            }
        }
    }
    __syncthreads();

    // Phase 3: row softmax (warp per row)
    for (int n = wid; n < 49; n += 4) {
        float* row = sa + n * AST;
        const float x0 = row[lane];
        const float x1 = (lane < 17) ? row[lane + 32] : -1e30f;
        float mx = fmaxf(x0, x1);
#pragma unroll
        for (int o = 16; o; o >>= 1) mx = fmaxf(mx, __shfl_xor_sync(0xffffffffu, mx, o));
        const float e0 = __expf(x0 - mx);
        const float e1 = (lane < 17) ? __expf(x1 - mx) : 0.f;
        float s = e0 + e1;
#pragma unroll
        for (int o = 16; o; o >>= 1) s += __shfl_xor_sync(0xffffffffu, s, o);
        const float inv = 1.f / s;
        row[lane] = e0 * inv;
        if (lane < 17) row[lane + 32] = e1 * inv;
    }
    __syncthreads();

    // Phase 4: out = attn @ V, tiles of 4 rows x float4 column
    for (int t = tid; t < 104; t += 128) {
        const int n0 = (t % 13) * 4;
        const int c4 = (t / 13) * 4;  // d offset 0..28
        float4 acc[4];
#pragma unroll
        for (int i = 0; i < 4; i++) acc[i] = make_float4(0.f, 0.f, 0.f, 0.f);
        for (int m = 0; m < 49; m++) {
            const float4 vv = *(const float4*)&sv[m * QST + c4];
#pragma unroll
            for (int i = 0; i < 4; i++) {
                const float p = sa[(n0 + i) * AST + m];
                acc[i].x += p * vv.x; acc[i].y += p * vv.y;
                acc[i].z += p * vv.z; acc[i].w += p * vv.w;
            }
        }
#pragma unroll
        for (int i = 0; i < 4; i++) {
            const int n = n0 + i;
            if (n < 49)
                *(float4*)(out + ((size_t)b * NTOK + n) * CDIM + hoff + c4) = acc[i];
        }
    }
}

// ---------------------------------------------------------------------------
extern "C" void kernel_launch(void* const* d_in, const int* in_sizes, int n_in,
                              void* d_out, int out_size)
{
    const float* x      = (const float*)d_in[0];
    const float* mask   = (const float*)d_in[1];
    const float* qkv_w  = (const float*)d_in[2];
    const float* qkv_b  = (const float*)d_in[3];
    const float* proj_w = (const float*)d_in[4];
    const float* proj_b = (const float*)d_in[5];
    const float* rpb    = (const float*)d_in[6];
    float* out = (float*)d_out;

    void* qkv_ptr = nullptr;
    void* att_ptr = nullptr;
    cudaGetSymbolAddress(&qkv_ptr, g_qkv);
    cudaGetSymbolAddress(&att_ptr, g_att);
    float* qkv_s = (float*)qkv_ptr;
    float* att_s = (float*)att_ptr;

    // 1) QKV GEMM: (200704,256) @ (768,256)^T + bias -> g_qkv (200704,768)
    {
        dim3 grid(3 * CDIM / BN, MROWS / BM);  // (6, 1568), x fastest for A reuse
        gemm_tf32_bias<<<grid, 256>>>(x, qkv_w, qkv_b, qkv_s, 3 * CDIM, CDIM);
    }
    // 2) windowed attention -> g_att (200704,256)
    win_attn<<<BWIN * NHEADS, 128>>>(qkv_s, mask, rpb, att_s);
    // 3) proj GEMM: (200704,256) @ (256,256)^T + bias -> out
    {
        dim3 grid(CDIM / BN, MROWS / BM);      // (2, 1568)
        gemm_tf32_bias<<<grid, 256>>>(att_s, proj_w, proj_b, out, CDIM, CDIM);
    }
}

// round 2
// speedup vs baseline: 1.2638x; 1.2638x over previous
#include <cuda_runtime.h>

#define NTOK   49
#define NHEADS 8
#define HDIM   32
#define CDIM   256
#define BWIN   4096
#define MROWS  (BWIN * NTOK)   /* 200704 */
#define NWIN   64

// Scratch (device-global arrays: allocation-free per harness rules)
__device__ float g_qkv[(size_t)MROWS * 3 * CDIM];   // (M, 768): col j = s*256 + h*32 + d
__device__ float g_att[(size_t)MROWS * CDIM];       // (M, 256): col = h*32 + d

__device__ __forceinline__ unsigned f2tf(float x) {
    unsigned u;
    asm("cvt.rna.tf32.f32 %0, %1;" : "=r"(u) : "f"(x));
    return u;
}
__device__ __forceinline__ float f2tff(float x) {
    return __uint_as_float(f2tf(x));
}

__device__ __forceinline__ void mma8(float* c, const unsigned* a, const unsigned* b) {
    asm volatile(
        "mma.sync.aligned.m16n8k8.row.col.f32.tf32.tf32.f32 "
        "{%0,%1,%2,%3}, {%4,%5,%6,%7}, {%8,%9}, {%0,%1,%2,%3};\n"
        : "+f"(c[0]), "+f"(c[1]), "+f"(c[2]), "+f"(c[3])
        : "r"(a[0]), "r"(a[1]), "r"(a[2]), "r"(a[3]), "r"(b[0]), "r"(b[1]));
}

// ---------------------------------------------------------------------------
// C[M,N] = A[M,K] @ B[N,K]^T + bias[N]   (all fp32 in gmem, tf32 mma compute)
// ---------------------------------------------------------------------------
#define BM 128
#define BN 128
#define BK 16
#define KST 20

__global__ __launch_bounds__(256, 2)
void gemm_tf32_bias(const float* __restrict__ A, const float* __restrict__ B,
                    const float* __restrict__ bias, float* __restrict__ C,
                    int N, int K)
{
    __shared__ unsigned As[BM * KST];
    __shared__ unsigned Bs[BN * KST];

    const int tid   = threadIdx.x;
    const int lane  = tid & 31;
    const int wid   = tid >> 5;
    const int g     = lane >> 2;
    const int tg    = lane & 3;
    const int warpM = wid & 1;
    const int warpN = wid >> 1;

    const float* Ab = A + (size_t)blockIdx.y * BM * K;
    const float* Bb = B + (size_t)blockIdx.x * BN * K;

    const int ldrow = tid >> 2;
    const int ldc4  = (tid & 3) << 2;

    float4 ra[2], rb[2];
#pragma unroll
    for (int i = 0; i < 2; i++) {
        ra[i] = *(const float4*)(Ab + (size_t)(ldrow + i * 64) * K + ldc4);
        rb[i] = *(const float4*)(Bb + (size_t)(ldrow + i * 64) * K + ldc4);
    }
#pragma unroll
    for (int i = 0; i < 2; i++) {
        const int r = ldrow + i * 64;
        uint4 ua = make_uint4(f2tf(ra[i].x), f2tf(ra[i].y), f2tf(ra[i].z), f2tf(ra[i].w));
        *(uint4*)&As[r * KST + ldc4] = ua;
        uint4 ub = make_uint4(f2tf(rb[i].x), f2tf(rb[i].y), f2tf(rb[i].z), f2tf(rb[i].w));
        *(uint4*)&Bs[r * KST + ldc4] = ub;
    }
    __syncthreads();

    float acc[4][4][4];
#pragma unroll
    for (int mt = 0; mt < 4; mt++)
#pragma unroll
        for (int nt = 0; nt < 4; nt++)
#pragma unroll
            for (int i = 0; i < 4; i++) acc[mt][nt][i] = 0.f;

    const int KT = K / BK;
    for (int kt = 0; kt < KT; kt++) {
        if (kt + 1 < KT) {
#pragma unroll
            for (int i = 0; i < 2; i++) {
                ra[i] = *(const float4*)(Ab + (size_t)(ldrow + i * 64) * K + (kt + 1) * BK + ldc4);
                rb[i] = *(const float4*)(Bb + (size_t)(ldrow + i * 64) * K + (kt + 1) * BK + ldc4);
            }
        }
#pragma unroll
        for (int k8 = 0; k8 < 2; k8++) {
            unsigned af[4][4], bf[4][2];
#pragma unroll
            for (int mt = 0; mt < 4; mt++) {
                const int base = (warpM * 64 + mt * 16 + g) * KST + k8 * 8 + tg;
                af[mt][0] = As[base];
                af[mt][1] = As[base + 8 * KST];
                af[mt][2] = As[base + 4];
                af[mt][3] = As[base + 8 * KST + 4];
            }
#pragma unroll
            for (int nt = 0; nt < 4; nt++) {
                const int base = (warpN * 32 + nt * 8 + g) * KST + k8 * 8 + tg;
                bf[nt][0] = Bs[base];
                bf[nt][1] = Bs[base + 4];
            }
#pragma unroll
            for (int mt = 0; mt < 4; mt++)
#pragma unroll
                for (int nt = 0; nt < 4; nt++)
                    mma8(acc[mt][nt], af[mt], bf[nt]);
        }
        __syncthreads();
        if (kt + 1 < KT) {
#pragma unroll
            for (int i = 0; i < 2; i++) {
                const int r = ldrow + i * 64;
                uint4 ua = make_uint4(f2tf(ra[i].x), f2tf(ra[i].y), f2tf(ra[i].z), f2tf(ra[i].w));
                *(uint4*)&As[r * KST + ldc4] = ua;
                uint4 ub = make_uint4(f2tf(rb[i].x), f2tf(rb[i].y), f2tf(rb[i].z), f2tf(rb[i].w));
                *(uint4*)&Bs[r * KST + ldc4] = ub;
            }
        }
        __syncthreads();
    }

#pragma unroll
    for (int mt = 0; mt < 4; mt++) {
        const int r = blockIdx.y * BM + warpM * 64 + mt * 16 + g;
#pragma unroll
        for (int nt = 0; nt < 4; nt++) {
            const int c = blockIdx.x * BN + warpN * 32 + nt * 8 + tg * 2;
            const float2 bb = *(const float2*)(bias + c);
            float2 lo = make_float2(acc[mt][nt][0] + bb.x, acc[mt][nt][1] + bb.y);
            float2 hi = make_float2(acc[mt][nt][2] + bb.x, acc[mt][nt][3] + bb.y);
            *(float2*)(C + (size_t)r * N + c)       = lo;
            *(float2*)(C + (size_t)(r + 8) * N + c) = hi;
        }
    }
}

// ---------------------------------------------------------------------------
// Window attention with tf32 mma.
// Block = (window b, head h). 4 warps; warp w owns Q rows [16w, 16w+16).
// QK^T: M=64(pad of 49) x N=56(pad) x K=32  -> 28 mma/warp
// softmax entirely in C-fragment registers (quad shfl reductions)
// P.V : M=16 x N=32 x K=56 -> 28 mma/warp
// smem layouts use a per-8 column-pair permute: perm(kk) = (kk&3)*2 + (kk>>2)
// so that fragment (tg, tg+4) pairs are contiguous -> LDS.64, banks distinct.
// ---------------------------------------------------------------------------
#define AT_QS 40   /* sq/sk row stride */
#define AT_VS 56   /* svT row stride  */
#define AT_AS 58   /* sa (bias, later P) row stride */

__global__ __launch_bounds__(128)
void win_attn_mma(const float* __restrict__ qkv, const float* __restrict__ mask,
                  const float* __restrict__ rpb, float* __restrict__ out)
{
    __shared__ float sq[64 * AT_QS];   // Q (pre-scaled, tf32), rows 49..63 zero
    __shared__ float sk[56 * AT_QS];   // K (tf32), rows 49..55 zero
    __shared__ float sv[32 * AT_VS];   // V^T (tf32): [d][token-permuted], cols 49..55 zero
    __shared__ float sa[64 * AT_AS];   // bias+mask, later reused for P

    const int b = blockIdx.x >> 3;
    const int h = blockIdx.x & 7;
    const int tid  = threadIdx.x;
    const int lane = tid & 31;
    const int w    = tid >> 5;
    const int g    = lane >> 2;
    const int tg   = lane & 3;
    const float scale = 0.17677669529663687f;  // 32^-0.5

    // ---- load q/k/v (permuted cols, tf32) ----
    const float* basep = qkv + (size_t)b * NTOK * 768 + h * HDIM;
    for (int idx = tid; idx < NTOK * HDIM; idx += 128) {
        const int n = idx >> 5, d = idx & 31;
        const int pc = ((d & 3) << 1) + ((d >> 2) & 1) + (d & ~7);
        const float* p = basep + (size_t)n * 768 + d;
        sq[n * AT_QS + pc] = f2tff(p[0] * scale);
        sk[n * AT_QS + pc] = f2tff(p[256]);
        const int pt = ((n & 3) << 1) + ((n >> 2) & 1) + (n & ~7);
        sv[d * AT_VS + pt] = f2tff(p[512]);
    }
    // ---- zero pads (only cols 0..31 of sq/sk are ever frag-read) ----
    for (int idx = tid; idx < 15 * 32; idx += 128) {
        sq[(49 + (idx >> 5)) * AT_QS + (idx & 31)] = 0.f;
    }
    for (int idx = tid; idx < 7 * 32; idx += 128) {
        sk[(49 + (idx >> 5)) * AT_QS + (idx & 31)] = 0.f;
    }
    for (int idx = tid; idx < 256; idx += 128) {
        const int d = idx >> 3, j = idx & 7;
        if (j < 7) sv[d * AT_VS + 49 + j] = 0.f;
    }
    // ---- bias+mask tile: rows 0..63 x cols 0..55 ----
    const float* mrow = mask + (size_t)(b & (NWIN - 1)) * (NTOK * NTOK);
    for (int idx = tid; idx < 64 * 56; idx += 128) {
        const int r = idx / 56, c = idx - r * 56;
        float v;
        if (c >= 49)      v = -1e30f;
        else if (r >= 49) v = 0.f;
        else {
            const int r1 = r / 7, c1 = r - r1 * 7;
            const int r2 = c / 7, c2 = c - r2 * 7;
            const int bi = (r1 - r2 + 6) * 13 + (c1 - c2 + 6);
            v = mrow[r * 49 + c] + rpb[bi * NHEADS + h];
        }
        sa[r * AT_AS + c] = v;
    }
    __syncthreads();

    const int r0 = w * 16 + g;    // first of this lane's two rows (other: r0+8)

    // ---- Q @ K^T ----
    unsigned aq[4][4];
#pragma unroll
    for (int kt = 0; kt < 4; kt++) {
        const float2 lo = *(const float2*)&sq[r0 * AT_QS + kt * 8 + tg * 2];
        const float2 hi = *(const float2*)&sq[(r0 + 8) * AT_QS + kt * 8 + tg * 2];
        aq[kt][0] = __float_as_uint(lo.x);
        aq[kt][1] = __float_as_uint(hi.x);
        aq[kt][2] = __float_as_uint(lo.y);
        aq[kt][3] = __float_as_uint(hi.y);
    }
    float c[7][4];
#pragma unroll
    for (int nt = 0; nt < 7; nt++)
#pragma unroll
        for (int i = 0; i < 4; i++) c[nt][i] = 0.f;

#pragma unroll
    for (int nt = 0; nt < 7; nt++) {
#pragma unroll
        for (int kt = 0; kt < 4; kt++) {
            const float2 bv = *(const float2*)&sk[(nt * 8 + g) * AT_QS + kt * 8 + tg * 2];
            unsigned bb[2] = { __float_as_uint(bv.x), __float_as_uint(bv.y) };
            mma8(c[nt], aq[kt], bb);
        }
    }

    // ---- + bias/mask, row max ----
    float mx0 = -1e30f, mx1 = -1e30f;
#pragma unroll
    for (int nt = 0; nt < 7; nt++) {
        const float2 b0 = *(const float2*)&sa[r0 * AT_AS + nt * 8 + tg * 2];
        const float2 b1 = *(const float2*)&sa[(r0 + 8) * AT_AS + nt * 8 + tg * 2];
        c[nt][0] += b0.x; c[nt][1] += b0.y;
        c[nt][2] += b1.x; c[nt][3] += b1.y;
        mx0 = fmaxf(mx0, fmaxf(c[nt][0], c[nt][1]));
        mx1 = fmaxf(mx1, fmaxf(c[nt][2], c[nt][3]));
    }
    mx0 = fmaxf(mx0, __shfl_xor_sync(0xffffffffu, mx0, 1));
    mx0 = fmaxf(mx0, __shfl_xor_sync(0xffffffffu, mx0, 2));
    mx1 = fmaxf(mx1, __shfl_xor_sync(0xffffffffu, mx1, 1));
    mx1 = fmaxf(mx1, __shfl_xor_sync(0xffffffffu, mx1, 2));

    // ---- exp + row sum ----
    float s0 = 0.f, s1 = 0.f;
#pragma unroll
    for (int nt = 0; nt < 7; nt++) {
        c[nt][0] = __expf(c[nt][0] - mx0);
        c[nt][1] = __expf(c[nt][1] - mx0);
        c[nt][2] = __expf(c[nt][2] - mx1);
        c[nt][3] = __expf(c[nt][3] - mx1);
        s0 += c[nt][0] + c[nt][1];
        s1 += c[nt][2] + c[nt][3];
    }
    s0 += __shfl_xor_sync(0xffffffffu, s0, 1);
    s0 += __shfl_xor_sync(0xffffffffu, s0, 2);
    s1 += __shfl_xor_sync(0xffffffffu, s1, 1);
    s1 += __shfl_xor_sync(0xffffffffu, s1, 2);
    const float i0 = 1.f / s0, i1 = 1.f / s1;

    // ---- write P into sa (this warp's rows only; bias reads for these rows done) ----
    __syncwarp();
#pragma unroll
    for (int nt = 0; nt < 7; nt++) {
        float2 p0 = make_float2(f2tff(c[nt][0] * i0), f2tff(c[nt][1] * i0));
        float2 p1 = make_float2(f2tff(c[nt][2] * i1), f2tff(c[nt][3] * i1));
        *(float2*)&sa[r0 * AT_AS + nt * 8 + tg * 2]       = p0;
        *(float2*)&sa[(r0 + 8) * AT_AS + nt * 8 + tg * 2] = p1;
    }
    __syncwarp();

    // ---- P @ V ----
    float cv[4][4];
#pragma unroll
    for (int nt = 0; nt < 4; nt++)
#pragma unroll
        for (int i = 0; i < 4; i++) cv[nt][i] = 0.f;

#pragma unroll
    for (int kt = 0; kt < 7; kt++) {
        unsigned ap[4];
        ap[0] = __float_as_uint(sa[r0 * AT_AS + kt * 8 + tg]);
        ap[1] = __float_as_uint(sa[(r0 + 8) * AT_AS + kt * 8 + tg]);
        ap[2] = __float_as_uint(sa[r0 * AT_AS + kt * 8 + tg + 4]);
        ap[3] = __float_as_uint(sa[(r0 + 8) * AT_AS + kt * 8 + tg + 4]);
#pragma unroll
        for (int nt = 0; nt < 4; nt++) {
            const float2 bv = *(const float2*)&sv[(nt * 8 + g) * AT_VS + kt * 8 + tg * 2];
            unsigned bb[2] = { __float_as_uint(bv.x), __float_as_uint(bv.y) };
            mma8(cv[nt], ap, bb);
        }
    }

    // ---- store out rows (<49) ----
    float* ob = out + (size_t)b * NTOK * CDIM + h * HDIM;
    if (r0 < NTOK) {
#pragma unroll
        for (int nt = 0; nt < 4; nt++)
            *(float2*)&ob[(size_t)r0 * CDIM + nt * 8 + tg * 2] =
                make_float2(cv[nt][0], cv[nt][1]);
    }
    if (r0 + 8 < NTOK) {
#pragma unroll
        for (int nt = 0; nt < 4; nt++)
            *(float2*)&ob[(size_t)(r0 + 8) * CDIM + nt * 8 + tg * 2] =
                make_float2(cv[nt][2], cv[nt][3]);
    }
}

// ---------------------------------------------------------------------------
extern "C" void kernel_launch(void* const* d_in, const int* in_sizes, int n_in,
                              void* d_out, int out_size)
{
    const float* x      = (const float*)d_in[0];
    const float* mask   = (const float*)d_in[1];
    const float* qkv_w  = (const float*)d_in[2];
    const float* qkv_b  = (const float*)d_in[3];
    const float* proj_w = (const float*)d_in[4];
    const float* proj_b = (const float*)d_in[5];
    const float* rpb    = (const float*)d_in[6];
    float* out = (float*)d_out;

    void* qkv_ptr = nullptr;
    void* att_ptr = nullptr;
    cudaGetSymbolAddress(&qkv_ptr, g_qkv);
    cudaGetSymbolAddress(&att_ptr, g_att);
    float* qkv_s = (float*)qkv_ptr;
    float* att_s = (float*)att_ptr;

    // 1) QKV GEMM: (200704,256) @ (768,256)^T + bias -> g_qkv
    {
        dim3 grid(3 * CDIM / BN, MROWS / BM);
        gemm_tf32_bias<<<grid, 256>>>(x, qkv_w, qkv_b, qkv_s, 3 * CDIM, CDIM);
    }
    // 2) windowed attention (tf32 mma) -> g_att
    win_attn_mma<<<BWIN * NHEADS, 128>>>(qkv_s, mask, rpb, att_s);
    // 3) proj GEMM: (200704,256) @ (256,256)^T + bias -> out
    {
        dim3 grid(CDIM / BN, MROWS / BM);
        gemm_tf32_bias<<<grid, 256>>>(att_s, proj_w, proj_b, out, CDIM, CDIM);
    }
}

// round 3
// speedup vs baseline: 1.4145x; 1.1193x over previous
#include <cuda_runtime.h>

#define NTOK   49
#define NHEADS 8
#define HDIM   32
#define CDIM   256
#define BWIN   4096
#define MROWS  (BWIN * NTOK)   /* 200704 */
#define NWIN   64

// Scratch (device-global arrays: allocation-free per harness rules)
// g_qkv: head-major chunks: [chunk = s*8+h][M = b*49+n][32], values tf32-rounded
__device__ float g_qkv[(size_t)MROWS * 3 * CDIM];
__device__ float g_att[(size_t)MROWS * CDIM];       // (M, 256) row-major f32

__device__ __forceinline__ unsigned f2tf(float x) {
    unsigned u;
    asm("cvt.rna.tf32.f32 %0, %1;" : "=r"(u) : "f"(x));
    return u;
}
__device__ __forceinline__ float f2tff(float x) {
    return __uint_as_float(f2tf(x));
}

__device__ __forceinline__ void mma8(float* c, const unsigned* a, const unsigned* b) {
    asm volatile(
        "mma.sync.aligned.m16n8k8.row.col.f32.tf32.tf32.f32 "
        "{%0,%1,%2,%3}, {%4,%5,%6,%7}, {%8,%9}, {%0,%1,%2,%3};\n"
        : "+f"(c[0]), "+f"(c[1]), "+f"(c[2]), "+f"(c[3])
        : "r"(a[0]), "r"(a[1]), "r"(a[2]), "r"(a[3]), "r"(b[0]), "r"(b[1]));
}

// ---------------------------------------------------------------------------
// C[M,N] = A[M,K] @ B[N,K]^T + bias[N]
// REMAP=0: row-major f32 output.  REMAP=1: head-major chunked + tf32-rounded.
// ---------------------------------------------------------------------------
#define BM 128
#define BN 128
#define BK 16
#define KST 20

template <int REMAP>
__global__ __launch_bounds__(256, 2)
void gemm_tf32_bias(const float* __restrict__ A, const float* __restrict__ B,
                    const float* __restrict__ bias, float* __restrict__ C,
                    int N, int K)
{
    __shared__ unsigned As[BM * KST];
    __shared__ unsigned Bs[BN * KST];

    const int tid   = threadIdx.x;
    const int lane  = tid & 31;
    const int wid   = tid >> 5;
    const int g     = lane >> 2;
    const int tg    = lane & 3;
    const int warpM = wid & 1;
    const int warpN = wid >> 1;

    const float* Ab = A + (size_t)blockIdx.y * BM * K;
    const float* Bb = B + (size_t)blockIdx.x * BN * K;

    const int ldrow = tid >> 2;
    const int ldc4  = (tid & 3) << 2;

    float4 ra[2], rb[2];
#pragma unroll
    for (int i = 0; i < 2; i++) {
        ra[i] = *(const float4*)(Ab + (size_t)(ldrow + i * 64) * K + ldc4);
        rb[i] = *(const float4*)(Bb + (size_t)(ldrow + i * 64) * K + ldc4);
    }
#pragma unroll
    for (int i = 0; i < 2; i++) {
        const int r = ldrow + i * 64;
        uint4 ua = make_uint4(f2tf(ra[i].x), f2tf(ra[i].y), f2tf(ra[i].z), f2tf(ra[i].w));
        *(uint4*)&As[r * KST + ldc4] = ua;
        uint4 ub = make_uint4(f2tf(rb[i].x), f2tf(rb[i].y), f2tf(rb[i].z), f2tf(rb[i].w));
        *(uint4*)&Bs[r * KST + ldc4] = ub;
    }
    __syncthreads();

    float acc[4][4][4];
#pragma unroll
    for (int mt = 0; mt < 4; mt++)
#pragma unroll
        for (int nt = 0; nt < 4; nt++)
#pragma unroll
            for (int i = 0; i < 4; i++) acc[mt][nt][i] = 0.f;

    const int KT = K / BK;
    for (int kt = 0; kt < KT; kt++) {
        if (kt + 1 < KT) {
#pragma unroll
            for (int i = 0; i < 2; i++) {
                ra[i] = *(const float4*)(Ab + (size_t)(ldrow + i * 64) * K + (kt + 1) * BK + ldc4);
                rb[i] = *(const float4*)(Bb + (size_t)(ldrow + i * 64) * K + (kt + 1) * BK + ldc4);
            }
        }
#pragma unroll
        for (int k8 = 0; k8 < 2; k8++) {
            unsigned af[4][4], bf[4][2];
#pragma unroll
            for (int mt = 0; mt < 4; mt++) {
                const int base = (warpM * 64 + mt * 16 + g) * KST + k8 * 8 + tg;
                af[mt][0] = As[base];
                af[mt][1] = As[base + 8 * KST];
                af[mt][2] = As[base + 4];
                af[mt][3] = As[base + 8 * KST + 4];
            }
#pragma unroll
            for (int nt = 0; nt < 4; nt++) {
                const int base = (warpN * 32 + nt * 8 + g) * KST + k8 * 8 + tg;
                bf[nt][0] = Bs[base];
                bf[nt][1] = Bs[base + 4];
            }
#pragma unroll
            for (int mt = 0; mt < 4; mt++)
#pragma unroll
                for (int nt = 0; nt < 4; nt++)
                    mma8(acc[mt][nt], af[mt], bf[nt]);
        }
        __syncthreads();
        if (kt + 1 < KT) {
#pragma unroll
            for (int i = 0; i < 2; i++) {
                const int r = ldrow + i * 64;
                uint4 ua = make_uint4(f2tf(ra[i].x), f2tf(ra[i].y), f2tf(ra[i].z), f2tf(ra[i].w));
                *(uint4*)&As[r * KST + ldc4] = ua;
                uint4 ub = make_uint4(f2tf(rb[i].x), f2tf(rb[i].y), f2tf(rb[i].z), f2tf(rb[i].w));
                *(uint4*)&Bs[r * KST + ldc4] = ub;
            }
        }
        __syncthreads();
    }

#pragma unroll
    for (int mt = 0; mt < 4; mt++) {
        const int r = blockIdx.y * BM + warpM * 64 + mt * 16 + g;
#pragma unroll
        for (int nt = 0; nt < 4; nt++) {
            const int j = blockIdx.x * BN + warpN * 32 + nt * 8 + tg * 2;
            const float2 bb = *(const float2*)(bias + j);
            if (REMAP) {
                // head-major chunk layout + tf32 rounding for the attention consumer
                const int chunk = j >> 5, wi = j & 31;
                float* d0 = C + ((size_t)chunk * MROWS + r) * HDIM + wi;
                float* d1 = C + ((size_t)chunk * MROWS + r + 8) * HDIM + wi;
                *(float2*)d0 = make_float2(f2tff(acc[mt][nt][0] + bb.x),
                                           f2tff(acc[mt][nt][1] + bb.y));
                *(float2*)d1 = make_float2(f2tff(acc[mt][nt][2] + bb.x),
                                           f2tff(acc[mt][nt][3] + bb.y));
            } else {
                float2 lo = make_float2(acc[mt][nt][0] + bb.x, acc[mt][nt][1] + bb.y);
                float2 hi = make_float2(acc[mt][nt][2] + bb.x, acc[mt][nt][3] + bb.y);
                *(float2*)(C + (size_t)r * N + j)       = lo;
                *(float2*)(C + (size_t)(r + 8) * N + j) = hi;
            }
        }
    }
}

// ---------------------------------------------------------------------------
// Window attention with tf32 mma. Inputs already tf32-rounded + head-major.
// ---------------------------------------------------------------------------
#define AT_QS 40
#define AT_VS 56
#define AT_AS 58

__global__ __launch_bounds__(128)
void win_attn_mma(const float* __restrict__ qkv, const float* __restrict__ mask,
                  const float* __restrict__ rpb, float* __restrict__ out)
{
    __shared__ float sq[64 * AT_QS];   // Q (tf32 bits), rows 49..63 zero
    __shared__ float sk[56 * AT_QS];   // K, rows 49..55 zero
    __shared__ float sv[32 * AT_VS];   // V^T: [d][token-permuted], cols 49..55 zero
    __shared__ float sa[64 * AT_AS];   // bias+mask, later reused for P

    const int b = blockIdx.x >> 3;
    const int h = blockIdx.x & 7;
    const int tid  = threadIdx.x;
    const int lane = tid & 31;
    const int w    = tid >> 5;
    const int g    = lane >> 2;
    const int tg   = lane & 3;
    const float scale = 0.17677669529663687f;  // 32^-0.5

    // ---- coalesced loads from head-major chunks ----
    const float* qb = qkv + ((size_t)h * MROWS + (size_t)b * NTOK) * HDIM;
    const float* kb = qkv + ((size_t)(8 + h) * MROWS + (size_t)b * NTOK) * HDIM;
    const float* vb = qkv + ((size_t)(16 + h) * MROWS + (size_t)b * NTOK) * HDIM;
    for (int idx = tid; idx < NTOK * 8; idx += 128) {   // 392 float4 per tensor
        const int n = idx >> 3, d4 = (idx & 7) << 2;
        const int pbase = (d4 & ~7) + ((d4 >> 2) & 1);  // col permute base, stride 2
        float4 v;
        v = *(const float4*)(qb + n * HDIM + d4);
        { float* d = &sq[n * AT_QS + pbase]; d[0] = v.x; d[2] = v.y; d[4] = v.z; d[6] = v.w; }
        v = *(const float4*)(kb + n * HDIM + d4);
        { float* d = &sk[n * AT_QS + pbase]; d[0] = v.x; d[2] = v.y; d[4] = v.z; d[6] = v.w; }
        v = *(const float4*)(vb + n * HDIM + d4);
        {
            const int pt = (n & ~7) + ((n & 3) << 1) + ((n >> 2) & 1);
            sv[(d4 + 0) * AT_VS + pt] = v.x;
            sv[(d4 + 1) * AT_VS + pt] = v.y;
            sv[(d4 + 2) * AT_VS + pt] = v.z;
            sv[(d4 + 3) * AT_VS + pt] = v.w;
        }
    }
    // ---- zero pads ----
    for (int idx = tid; idx < 15 * 32; idx += 128)
        sq[(49 + (idx >> 5)) * AT_QS + (idx & 31)] = 0.f;
    for (int idx = tid; idx < 7 * 32; idx += 128)
        sk[(49 + (idx >> 5)) * AT_QS + (idx & 31)] = 0.f;
    for (int idx = tid; idx < 256; idx += 128) {
        const int d = idx >> 3, j = idx & 7;
        if (j < 7) sv[d * AT_VS + 49 + j] = 0.f;
    }
    // ---- bias+mask tile ----
    const float* mrow = mask + (size_t)(b & (NWIN - 1)) * (NTOK * NTOK);
    for (int idx = tid; idx < 64 * 56; idx += 128) {
        const int r = idx / 56, c = idx - r * 56;
        float v;
        if (c >= 49)      v = -1e30f;
        else if (r >= 49) v = 0.f;
        else {
            const int r1 = r / 7, c1 = r - r1 * 7;
            const int r2 = c / 7, c2 = c - r2 * 7;
            const int bi = (r1 - r2 + 6) * 13 + (c1 - c2 + 6);
            v = mrow[r * 49 + c] + rpb[bi * NHEADS + h];
        }
        sa[r * AT_AS + c] = v;
    }
    __syncthreads();

    const int r0 = w * 16 + g;

    // ---- Q @ K^T ----
    unsigned aq[4][4];
#pragma unroll
    for (int kt = 0; kt < 4; kt++) {
        const float2 lo = *(const float2*)&sq[r0 * AT_QS + kt * 8 + tg * 2];
        const float2 hi = *(const float2*)&sq[(r0 + 8) * AT_QS + kt * 8 + tg * 2];
        aq[kt][0] = __float_as_uint(lo.x);
        aq[kt][1] = __float_as_uint(hi.x);
        aq[kt][2] = __float_as_uint(lo.y);
        aq[kt][3] = __float_as_uint(hi.y);
    }
    float c[7][4];
#pragma unroll
    for (int nt = 0; nt < 7; nt++)
#pragma unroll
        for (int i = 0; i < 4; i++) c[nt][i] = 0.f;

#pragma unroll
    for (int nt = 0; nt < 7; nt++) {
#pragma unroll
        for (int kt = 0; kt < 4; kt++) {
            const float2 bv = *(const float2*)&sk[(nt * 8 + g) * AT_QS + kt * 8 + tg * 2];
            unsigned bb[2] = { __float_as_uint(bv.x), __float_as_uint(bv.y) };
            mma8(c[nt], aq[kt], bb);
        }
    }

    // ---- scale (exact, in f32) + bias/mask, row max ----
    float mx0 = -1e30f, mx1 = -1e30f;
#pragma unroll
    for (int nt = 0; nt < 7; nt++) {
        const float2 b0 = *(const float2*)&sa[r0 * AT_AS + nt * 8 + tg * 2];
        const float2 b1 = *(const float2*)&sa[(r0 + 8) * AT_AS + nt * 8 + tg * 2];
        c[nt][0] = fmaf(c[nt][0], scale, b0.x);
        c[nt][1] = fmaf(c[nt][1], scale, b0.y);
        c[nt][2] = fmaf(c[nt][2], scale, b1.x);
        c[nt][3] = fmaf(c[nt][3], scale, b1.y);
        mx0 = fmaxf(mx0, fmaxf(c[nt][0], c[nt][1]));
        mx1 = fmaxf(mx1, fmaxf(c[nt][2], c[nt][3]));
    }
    mx0 = fmaxf(mx0, __shfl_xor_sync(0xffffffffu, mx0, 1));
    mx0 = fmaxf(mx0, __shfl_xor_sync(0xffffffffu, mx0, 2));
    mx1 = fmaxf(mx1, __shfl_xor_sync(0xffffffffu, mx1, 1));
    mx1 = fmaxf(mx1, __shfl_xor_sync(0xffffffffu, mx1, 2));

    // ---- exp + row sum ----
    float s0 = 0.f, s1 = 0.f;
#pragma unroll
    for (int nt = 0; nt < 7; nt++) {
        c[nt][0] = __expf(c[nt][0] - mx0);
        c[nt][1] = __expf(c[nt][1] - mx0);
        c[nt][2] = __expf(c[nt][2] - mx1);
        c[nt][3] = __expf(c[nt][3] - mx1);
        s0 += c[nt][0] + c[nt][1];
        s1 += c[nt][2] + c[nt][3];
    }
    s0 += __shfl_xor_sync(0xffffffffu, s0, 1);
    s0 += __shfl_xor_sync(0xffffffffu, s0, 2);
    s1 += __shfl_xor_sync(0xffffffffu, s1, 1);
    s1 += __shfl_xor_sync(0xffffffffu, s1, 2);
    const float i0 = 1.f / s0, i1 = 1.f / s1;

    // ---- write P into sa ----
    __syncwarp();
#pragma unroll
    for (int nt = 0; nt < 7; nt++) {
        float2 p0 = make_float2(f2tff(c[nt][0] * i0), f2tff(c[nt][1] * i0));
        float2 p1 = make_float2(f2tff(c[nt][2] * i1), f2tff(c[nt][3] * i1));
        *(float2*)&sa[r0 * AT_AS + nt * 8 + tg * 2]       = p0;
        *(float2*)&sa[(r0 + 8) * AT_AS + nt * 8 + tg * 2] = p1;
    }
    __syncwarp();

    // ---- P @ V ----
    float cv[4][4];
#pragma unroll
    for (int nt = 0; nt < 4; nt++)
#pragma unroll
        for (int i = 0; i < 4; i++) cv[nt][i] = 0.f;

#pragma unroll
    for (int kt = 0; kt < 7; kt++) {
        unsigned ap[4];
        ap[0] = __float_as_uint(sa[r0 * AT_AS + kt * 8 + tg]);
        ap[1] = __float_as_uint(sa[(r0 + 8) * AT_AS + kt * 8 + tg]);
        ap[2] = __float_as_uint(sa[r0 * AT_AS + kt * 8 + tg + 4]);
        ap[3] = __float_as_uint(sa[(r0 + 8) * AT_AS + kt * 8 + tg + 4]);
#pragma unroll
        for (int nt = 0; nt < 4; nt++) {
            const float2 bv = *(const float2*)&sv[(nt * 8 + g) * AT_VS + kt * 8 + tg * 2];
            unsigned bb[2] = { __float_as_uint(bv.x), __float_as_uint(bv.y) };
            mma8(cv[nt], ap, bb);
        }
    }

    // ---- store out rows (<49), row-major for proj GEMM ----
    float* ob = out + (size_t)b * NTOK * CDIM + h * HDIM;
    if (r0 < NTOK) {
#pragma unroll
        for (int nt = 0; nt < 4; nt++)
            *(float2*)&ob[(size_t)r0 * CDIM + nt * 8 + tg * 2] =
                make_float2(cv[nt][0], cv[nt][1]);
    }
    if (r0 + 8 < NTOK) {
#pragma unroll
        for (int nt = 0; nt < 4; nt++)
            *(float2*)&ob[(size_t)(r0 + 8) * CDIM + nt * 8 + tg * 2] =
                make_float2(cv[nt][2], cv[nt][3]);
    }
}

// ---------------------------------------------------------------------------
extern "C" void kernel_launch(void* const* d_in, const int* in_sizes, int n_in,
                              void* d_out, int out_size)
{
    const float* x      = (const float*)d_in[0];
    const float* mask   = (const float*)d_in[1];
    const float* qkv_w  = (const float*)d_in[2];
    const float* qkv_b  = (const float*)d_in[3];
    const float* proj_w = (const float*)d_in[4];
    const float* proj_b = (const float*)d_in[5];
    const float* rpb    = (const float*)d_in[6];
    float* out = (float*)d_out;

    void* qkv_ptr = nullptr;
    void* att_ptr = nullptr;
    cudaGetSymbolAddress(&qkv_ptr, g_qkv);
    cudaGetSymbolAddress(&att_ptr, g_att);
    float* qkv_s = (float*)qkv_ptr;
    float* att_s = (float*)att_ptr;

    // 1) QKV GEMM -> head-major tf32-rounded scratch
    {
        dim3 grid(3 * CDIM / BN, MROWS / BM);
        gemm_tf32_bias<1><<<grid, 256>>>(x, qkv_w, qkv_b, qkv_s, 3 * CDIM, CDIM);
    }
    // 2) windowed attention (tf32 mma) -> g_att
    win_attn_mma<<<BWIN * NHEADS, 128>>>(qkv_s, mask, rpb, att_s);
    // 3) proj GEMM -> out (row-major f32)
    {
        dim3 grid(CDIM / BN, MROWS / BM);
        gemm_tf32_bias<0><<<grid, 256>>>(att_s, proj_w, proj_b, out, CDIM, CDIM);
    }
}

// round 5
// speedup vs baseline: 1.6118x; 1.1395x over previous
#include <cuda_runtime.h>

#define NTOK   49
#define NHEADS 8
#define HDIM   32
#define CDIM   256
#define BWIN   4096
#define MROWS  (BWIN * NTOK)   /* 200704 */
#define NWIN   64

// Scratch (device-global arrays: allocation-free per harness rules)
// g_qkv: head-major chunks: [chunk = s*8+h][M = b*49+n][32], values tf32-rounded
__device__ float g_qkv[(size_t)MROWS * 3 * CDIM];
__device__ float g_att[(size_t)MROWS * CDIM];       // (M, 256) row-major f32
// precomputed bias+mask tiles: [(h*64+bmod)][64 rows][64 cols] (cols 56.. junk)
__device__ float g_bias[512 * 64 * 64];

__device__ __forceinline__ unsigned f2tf(float x) {
    unsigned u;
    asm("cvt.rna.tf32.f32 %0, %1;" : "=r"(u) : "f"(x));
    return u;
}
__device__ __forceinline__ float f2tff(float x) {
    return __uint_as_float(f2tf(x));
}

__device__ __forceinline__ void mma8(float* c, const unsigned* a, const unsigned* b) {
    asm volatile(
        "mma.sync.aligned.m16n8k8.row.col.f32.tf32.tf32.f32 "
        "{%0,%1,%2,%3}, {%4,%5,%6,%7}, {%8,%9}, {%0,%1,%2,%3};\n"
        : "+f"(c[0]), "+f"(c[1]), "+f"(c[2]), "+f"(c[3])
        : "r"(a[0]), "r"(a[1]), "r"(a[2]), "r"(a[3]), "r"(b[0]), "r"(b[1]));
}

// ---------------------------------------------------------------------------
// C[M,N] = A[M,256] @ B[N,256]^T + bias[N]   (tf32 legacy mma, K=256 fixed)
// Block tile 128x256, 8 warps in 2Mx4N grid, warp tile 64x64.
// REMAP=0: row-major f32 output.  REMAP=1: head-major chunked + tf32-rounded.
// ---------------------------------------------------------------------------
#define BK 16
#define KST 20

template <int REMAP>
__global__ __launch_bounds__(256)
void gemm_tf32_bias(const float* __restrict__ A, const float* __restrict__ B,
                    const float* __restrict__ bias, float* __restrict__ C,
                    int N)
{
    __shared__ unsigned As[128 * KST];
    __shared__ unsigned Bs[256 * KST];

    const int tid   = threadIdx.x;
    const int lane  = tid & 31;
    const int wid   = tid >> 5;
    const int g     = lane >> 2;
    const int tg    = lane & 3;
    const int warpM = wid & 1;     // 2 warps along M (64 rows each)
    const int warpN = wid >> 1;    // 4 warps along N (64 cols each)

    const float* Ab = A + (size_t)blockIdx.y * 128 * 256;
    const float* Bb = B + (size_t)blockIdx.x * 256 * 256;

    const int ldrow = tid >> 2;        // 0..63
    const int ldc4  = (tid & 3) << 2;  // 0,4,8,12

    float4 ra[2], rb[4];
#pragma unroll
    for (int i = 0; i < 2; i++)
        ra[i] = *(const float4*)(Ab + (size_t)(ldrow + i * 64) * 256 + ldc4);
#pragma unroll
    for (int i = 0; i < 4; i++)
        rb[i] = *(const float4*)(Bb + (size_t)(ldrow + i * 64) * 256 + ldc4);
#pragma unroll
    for (int i = 0; i < 2; i++)
        *(uint4*)&As[(ldrow + i * 64) * KST + ldc4] =
            make_uint4(f2tf(ra[i].x), f2tf(ra[i].y), f2tf(ra[i].z), f2tf(ra[i].w));
#pragma unroll
    for (int i = 0; i < 4; i++)
        *(uint4*)&Bs[(ldrow + i * 64) * KST + ldc4] =
            make_uint4(f2tf(rb[i].x), f2tf(rb[i].y), f2tf(rb[i].z), f2tf(rb[i].w));
    __syncthreads();

    float acc[4][8][4];
#pragma unroll
    for (int mt = 0; mt < 4; mt++)
#pragma unroll
        for (int nt = 0; nt < 8; nt++)
#pragma unroll
            for (int i = 0; i < 4; i++) acc[mt][nt][i] = 0.f;

    for (int kt = 0; kt < 16; kt++) {
        if (kt + 1 < 16) {
#pragma unroll
            for (int i = 0; i < 2; i++)
                ra[i] = *(const float4*)(Ab + (size_t)(ldrow + i * 64) * 256 + (kt + 1) * BK + ldc4);
#pragma unroll
            for (int i = 0; i < 4; i++)
                rb[i] = *(const float4*)(Bb + (size_t)(ldrow + i * 64) * 256 + (kt + 1) * BK + ldc4);
        }
#pragma unroll
        for (int k8 = 0; k8 < 2; k8++) {
            unsigned af[4][4], bf[8][2];
#pragma unroll
            for (int mt = 0; mt < 4; mt++) {
                const int base = (warpM * 64 + mt * 16 + g) * KST + k8 * 8 + tg;
                af[mt][0] = As[base];
                af[mt][1] = As[base + 8 * KST];
                af[mt][2] = As[base + 4];
                af[mt][3] = As[base + 8 * KST + 4];
            }
#pragma unroll
            for (int nt = 0; nt < 8; nt++) {
                const int base = (warpN * 64 + nt * 8 + g) * KST + k8 * 8 + tg;
                bf[nt][0] = Bs[base];
                bf[nt][1] = Bs[base + 4];
            }
#pragma unroll
            for (int mt = 0; mt < 4; mt++)
#pragma unroll
                for (int nt = 0; nt < 8; nt++)
                    mma8(acc[mt][nt], af[mt], bf[nt]);
        }
        __syncthreads();
        if (kt + 1 < 16) {
#pragma unroll
            for (int i = 0; i < 2; i++)
                *(uint4*)&As[(ldrow + i * 64) * KST + ldc4] =
                    make_uint4(f2tf(ra[i].x), f2tf(ra[i].y), f2tf(ra[i].z), f2tf(ra[i].w));
#pragma unroll
            for (int i = 0; i < 4; i++)
                *(uint4*)&Bs[(ldrow + i * 64) * KST + ldc4] =
                    make_uint4(f2tf(rb[i].x), f2tf(rb[i].y), f2tf(rb[i].z), f2tf(rb[i].w));
        }
        __syncthreads();
    }

#pragma unroll
    for (int mt = 0; mt < 4; mt++) {
        const int r = blockIdx.y * 128 + warpM * 64 + mt * 16 + g;
#pragma unroll
        for (int nt = 0; nt < 8; nt++) {
            const int j = blockIdx.x * 256 + warpN * 64 + nt * 8 + tg * 2;
            const float2 bb = *(const float2*)(bias + j);
            if (REMAP) {
                const int chunk = j >> 5, wi = j & 31;
                float* d0 = C + ((size_t)chunk * MROWS + r) * HDIM + wi;
                float* d1 = C + ((size_t)chunk * MROWS + r + 8) * HDIM + wi;
                *(float2*)d0 = make_float2(f2tff(acc[mt][nt][0] + bb.x),
                                           f2tff(acc[mt][nt][1] + bb.y));
                *(float2*)d1 = make_float2(f2tff(acc[mt][nt][2] + bb.x),
                                           f2tff(acc[mt][nt][3] + bb.y));
            } else {
                *(float2*)(C + (size_t)r * N + j) =
                    make_float2(acc[mt][nt][0] + bb.x, acc[mt][nt][1] + bb.y);
                *(float2*)(C + (size_t)(r + 8) * N + j) =
                    make_float2(acc[mt][nt][2] + bb.x, acc[mt][nt][3] + bb.y);
            }
        }
    }
}

// ---------------------------------------------------------------------------
// Precompute bias+mask tiles: tile t = (h*64 + bmod), 64x64 floats.
// ---------------------------------------------------------------------------
__global__ __launch_bounds__(128)
void prep_bias(const float* __restrict__ mask, const float* __restrict__ rpb,
               float* __restrict__ gb)
{
    const int t = blockIdx.x;
    const int h = t >> 6, bm = t & 63;
    const float* mrow = mask + (size_t)bm * (NTOK * NTOK);
    float* dst = gb + (size_t)t * 4096;
    for (int idx = threadIdx.x; idx < 4096; idx += 128) {
        const int r = idx >> 6, c = idx & 63;
        float v;
        if (c >= 49)      v = -1e30f;
        else if (r >= 49) v = 0.f;
        else {
            const int r1 = r / 7, c1 = r - r1 * 7;
            const int r2 = c / 7, c2 = c - r2 * 7;
            const int bi = (r1 - r2 + 6) * 13 + (c1 - c2 + 6);
            v = mrow[r * 49 + c] + rpb[bi * NHEADS + h];
        }
        dst[idx] = v;
    }
}

// ---------------------------------------------------------------------------
// Window attention with tf32 mma (legacy m16n8k8). Inputs tf32 + head-major.
// ---------------------------------------------------------------------------
#define AT_QS 40
#define AT_VS 56
#define AT_AS 60

__global__ __launch_bounds__(128)
void win_attn_mma(const float* __restrict__ qkv, const float* __restrict__ gbias,
                  float* __restrict__ out)
{
    __shared__ float sq[64 * AT_QS];
    __shared__ float sk[56 * AT_QS];
    __shared__ float sv[32 * AT_VS];
    __shared__ float sa[64 * AT_AS];

    const int b = blockIdx.x >> 3;
    const int h = blockIdx.x & 7;
    const int tid  = threadIdx.x;
    const int lane = tid & 31;
    const int w    = tid >> 5;
    const int g    = lane >> 2;
    const int tg   = lane & 3;
    const float scale = 0.17677669529663687f;

    // ---- coalesced loads from head-major chunks ----
    const float* qb = qkv + ((size_t)h * MROWS + (size_t)b * NTOK) * HDIM;
    const float* kb = qkv + ((size_t)(8 + h) * MROWS + (size_t)b * NTOK) * HDIM;
    const float* vb = qkv + ((size_t)(16 + h) * MROWS + (size_t)b * NTOK) * HDIM;
    for (int idx = tid; idx < NTOK * 8; idx += 128) {
        const int n = idx >> 3, d4 = (idx & 7) << 2;
        const int pbase = (d4 & ~7) + ((d4 >> 2) & 1);
        float4 v;
        v = *(const float4*)(qb + n * HDIM + d4);
        { float* d = &sq[n * AT_QS + pbase]; d[0] = v.x; d[2] = v.y; d[4] = v.z; d[6] = v.w; }
        v = *(const float4*)(kb + n * HDIM + d4);
        { float* d = &sk[n * AT_QS + pbase]; d[0] = v.x; d[2] = v.y; d[4] = v.z; d[6] = v.w; }
        v = *(const float4*)(vb + n * HDIM + d4);
        {
            const int pt = (n & ~7) + ((n & 3) << 1) + ((n >> 2) & 1);
            sv[(d4 + 0) * AT_VS + pt] = v.x;
            sv[(d4 + 1) * AT_VS + pt] = v.y;
            sv[(d4 + 2) * AT_VS + pt] = v.z;
            sv[(d4 + 3) * AT_VS + pt] = v.w;
        }
    }
    // ---- bias tile: coalesced float4 from precomputed table ----
    const float* bt = gbias + ((size_t)((h << 6) | (b & 63))) * 4096;
#pragma unroll
    for (int j = 0; j < 8; j++) {
        const int idx = tid + j * 128;            // 0..1023 float4s
        const int r = idx >> 4, c4 = (idx & 15) << 2;
        if (c4 < 56)
            *(float4*)&sa[r * AT_AS + c4] = *(const float4*)(bt + (idx << 2));
    }
    // ---- zero pads ----
    for (int idx = tid; idx < 15 * 32; idx += 128)
        sq[(49 + (idx >> 5)) * AT_QS + (idx & 31)] = 0.f;
    for (int idx = tid; idx < 7 * 32; idx += 128)
        sk[(49 + (idx >> 5)) * AT_QS + (idx & 31)] = 0.f;
    for (int idx = tid; idx < 256; idx += 128) {
        const int d = idx >> 3, j = idx & 7;
        if (j < 7) sv[d * AT_VS + 49 + j] = 0.f;
    }
    __syncthreads();

    const int r0 = w * 16 + g;

    // ---- Q @ K^T ----
    unsigned aq[4][4];
#pragma unroll
    for (int kt = 0; kt < 4; kt++) {
        const float2 lo = *(const float2*)&sq[r0 * AT_QS + kt * 8 + tg * 2];
        const float2 hi = *(const float2*)&sq[(r0 + 8) * AT_QS + kt * 8 + tg * 2];
        aq[kt][0] = __float_as_uint(lo.x);
        aq[kt][1] = __float_as_uint(hi.x);
        aq[kt][2] = __float_as_uint(lo.y);
        aq[kt][3] = __float_as_uint(hi.y);
    }
    float c[7][4];
#pragma unroll
    for (int nt = 0; nt < 7; nt++)
#pragma unroll
        for (int i = 0; i < 4; i++) c[nt][i] = 0.f;

#pragma unroll
    for (int nt = 0; nt < 7; nt++) {
#pragma unroll
        for (int kt = 0; kt < 4; kt++) {
            const float2 bv = *(const float2*)&sk[(nt * 8 + g) * AT_QS + kt * 8 + tg * 2];
            unsigned bb[2] = { __float_as_uint(bv.x), __float_as_uint(bv.y) };
            mma8(c[nt], aq[kt], bb);
        }
    }

    // ---- scale + bias/mask, row max ----
    float mx0 = -1e30f, mx1 = -1e30f;
#pragma unroll
    for (int nt = 0; nt < 7; nt++) {
        const float2 b0 = *(const float2*)&sa[r0 * AT_AS + nt * 8 + tg * 2];
        const float2 b1 = *(const float2*)&sa[(r0 + 8) * AT_AS + nt * 8 + tg * 2];
        c[nt][0] = fmaf(c[nt][0], scale, b0.x);
        c[nt][1] = fmaf(c[nt][1], scale, b0.y);
        c[nt][2] = fmaf(c[nt][2], scale, b1.x);
        c[nt][3] = fmaf(c[nt][3], scale, b1.y);
        mx0 = fmaxf(mx0, fmaxf(c[nt][0], c[nt][1]));
        mx1 = fmaxf(mx1, fmaxf(c[nt][2], c[nt][3]));
    }
    mx0 = fmaxf(mx0, __shfl_xor_sync(0xffffffffu, mx0, 1));
    mx0 = fmaxf(mx0, __shfl_xor_sync(0xffffffffu, mx0, 2));
    mx1 = fmaxf(mx1, __shfl_xor_sync(0xffffffffu, mx1, 1));
    mx1 = fmaxf(mx1, __shfl_xor_sync(0xffffffffu, mx1, 2));

    // ---- exp + row sum ----
    float s0 = 0.f, s1 = 0.f;
#pragma unroll
    for (int nt = 0; nt < 7; nt++) {
        c[nt][0] = __expf(c[nt][0] - mx0);
        c[nt][1] = __expf(c[nt][1] - mx0);
        c[nt][2] = __expf(c[nt][2] - mx1);
        c[nt][3] = __expf(c[nt][3] - mx1);
        s0 += c[nt][0] + c[nt][1];
        s1 += c[nt][2] + c[nt][3];
    }
    s0 += __shfl_xor_sync(0xffffffffu, s0, 1);
    s0 += __shfl_xor_sync(0xffffffffu, s0, 2);
    s1 += __shfl_xor_sync(0xffffffffu, s1, 1);
    s1 += __shfl_xor_sync(0xffffffffu, s1, 2);
    const float i0 = 1.f / s0, i1 = 1.f / s1;

    // ---- write P into sa ----
    __syncwarp();
#pragma unroll
    for (int nt = 0; nt < 7; nt++) {
        float2 p0 = make_float2(f2tff(c[nt][0] * i0), f2tff(c[nt][1] * i0));
        float2 p1 = make_float2(f2tff(c[nt][2] * i1), f2tff(c[nt][3] * i1));
        *(float2*)&sa[r0 * AT_AS + nt * 8 + tg * 2]       = p0;
        *(float2*)&sa[(r0 + 8) * AT_AS + nt * 8 + tg * 2] = p1;
    }
    __syncwarp();

    // ---- P @ V ----
    float cv[4][4];
#pragma unroll
    for (int nt = 0; nt < 4; nt++)
#pragma unroll
        for (int i = 0; i < 4; i++) cv[nt][i] = 0.f;

#pragma unroll
    for (int kt = 0; kt < 7; kt++) {
        unsigned ap[4];
        ap[0] = __float_as_uint(sa[r0 * AT_AS + kt * 8 + tg]);
        ap[1] = __float_as_uint(sa[(r0 + 8) * AT_AS + kt * 8 + tg]);
        ap[2] = __float_as_uint(sa[r0 * AT_AS + kt * 8 + tg + 4]);
        ap[3] = __float_as_uint(sa[(r0 + 8) * AT_AS + kt * 8 + tg + 4]);
#pragma unroll
        for (int nt = 0; nt < 4; nt++) {
            const float2 bv = *(const float2*)&sv[(nt * 8 + g) * AT_VS + kt * 8 + tg * 2];
            unsigned bb[2] = { __float_as_uint(bv.x), __float_as_uint(bv.y) };
            mma8(cv[nt], ap, bb);
        }
    }

    // ---- store out rows (<49), row-major for proj GEMM ----
    float* ob = out + (size_t)b * NTOK * CDIM + h * HDIM;
    if (r0 < NTOK) {
#pragma unroll
        for (int nt = 0; nt < 4; nt++)
            *(float2*)&ob[(size_t)r0 * CDIM + nt * 8 + tg * 2] =
                make_float2(cv[nt][0], cv[nt][1]);
    }
    if (r0 + 8 < NTOK) {
#pragma unroll
        for (int nt = 0; nt < 4; nt++)
            *(float2*)&ob[(size_t)(r0 + 8) * CDIM + nt * 8 + tg * 2] =
                make_float2(cv[nt][2], cv[nt][3]);
    }
}

// ---------------------------------------------------------------------------
extern "C" void kernel_launch(void* const* d_in, const int* in_sizes, int n_in,
                              void* d_out, int out_size)
{
    const float* x      = (const float*)d_in[0];
    const float* mask   = (const float*)d_in[1];
    const float* qkv_w  = (const float*)d_in[2];
    const float* qkv_b  = (const float*)d_in[3];
    const float* proj_w = (const float*)d_in[4];
    const float* proj_b = (const float*)d_in[5];
    const float* rpb    = (const float*)d_in[6];
    float* out = (float*)d_out;

    void *qkv_ptr = nullptr, *att_ptr = nullptr, *bias_ptr = nullptr;
    cudaGetSymbolAddress(&qkv_ptr, g_qkv);
    cudaGetSymbolAddress(&att_ptr, g_att);
    cudaGetSymbolAddress(&bias_ptr, g_bias);
    float* qkv_s  = (float*)qkv_ptr;
    float* att_s  = (float*)att_ptr;
    float* bias_s = (float*)bias_ptr;

    // 0) precompute bias+mask tiles (independent of GEMM)
    prep_bias<<<512, 128>>>(mask, rpb, bias_s);
    // 1) QKV GEMM -> head-major tf32-rounded scratch
    gemm_tf32_bias<1><<<dim3(3, MROWS / 128), 256>>>(x, qkv_w, qkv_b, qkv_s, 3 * CDIM);
    // 2) windowed attention (tf32 mma) -> g_att
    win_attn_mma<<<BWIN * NHEADS, 128>>>(qkv_s, bias_s, att_s);
    // 3) proj GEMM -> out (row-major f32)
    gemm_tf32_bias<0><<<dim3(1, MROWS / 128), 256>>>(att_s, proj_w, proj_b, out, CDIM);
}

// round 7
// speedup vs baseline: 1.6919x; 1.0497x over previous
#include <cuda_runtime.h>

#define NTOK   49
#define NHEADS 8
#define HDIM   32
#define CDIM   256
#define BWIN   4096
#define MROWS  (BWIN * NTOK)   /* 200704 */
#define NWIN   64

// Scratch (device-global arrays: allocation-free per harness rules)
__device__ float g_qkv[(size_t)MROWS * 3 * CDIM];   // head-major chunks
__device__ float g_att[(size_t)MROWS * CDIM];       // (M, 256) row-major f32
__device__ float g_bias[512 * 64 * 64];             // bias+mask tiles

__device__ __forceinline__ unsigned f2tf(float x) {
    unsigned u;
    asm("cvt.rna.tf32.f32 %0, %1;" : "=r"(u) : "f"(x));
    return u;
}
__device__ __forceinline__ float f2tff(float x) {
    return __uint_as_float(f2tf(x));
}
__device__ __forceinline__ unsigned smem_u32(const void* p) {
    unsigned a;
    asm("{ .reg .u64 t; cvta.to.shared.u64 t, %1; cvt.u32.u64 %0, t; }" : "=r"(a) : "l"(p));
    return a;
}
__device__ __forceinline__ void cp16(unsigned dst, const float* src) {
    asm volatile("cp.async.cg.shared.global [%0], [%1], 16;" :: "r"(dst), "l"(src));
}

__device__ __forceinline__ void mma8(float* c, const unsigned* a, const unsigned* b) {
    asm volatile(
        "mma.sync.aligned.m16n8k8.row.col.f32.tf32.tf32.f32 "
        "{%0,%1,%2,%3}, {%4,%5,%6,%7}, {%8,%9}, {%0,%1,%2,%3};\n"
        : "+f"(c[0]), "+f"(c[1]), "+f"(c[2]), "+f"(c[3])
        : "r"(a[0]), "r"(a[1]), "r"(a[2]), "r"(a[3]), "r"(b[0]), "r"(b[1]));
}

// ---------------------------------------------------------------------------
// C[M,N] = A[M,256] @ B[N,256]^T + bias[N]   (f32 gmem, tf32 mma)
// Block 128x128, 8 warps (2M x 4N), warp tile 64x32, 2 CTAs/SM.
// 4-stage cp.async.cg pipeline; cvt.rna applied post-LDS in the fragment path.
// REMAP=1: head-major chunked + tf32-rounded output.  REMAP=0: row-major f32.
// ---------------------------------------------------------------------------
#define KST 20
#define A_FLOATS (128 * KST)           /* 2560 floats = 10240 B */
#define STAGE_FLOATS (2 * A_FLOATS)    /* A + B */
#define STAGE_BYTES (STAGE_FLOATS * 4) /* 20480 B */
#define NSTAGE 4
#define GEMM_SMEM (NSTAGE * STAGE_BYTES) /* 81920 B */

template <int REMAP>
__global__ __launch_bounds__(256, 2)
void gemm_ca(const float* __restrict__ A, const float* __restrict__ B,
             const float* __restrict__ bias, float* __restrict__ C, int N)
{
    extern __shared__ float smf[];
    const unsigned sbase = smem_u32(smf);

    const int tid   = threadIdx.x;
    const int lane  = tid & 31;
    const int wid   = tid >> 5;
    const int g     = lane >> 2;
    const int tg    = lane & 3;
    const int warpM = wid & 1;     // 2 warps along M (64 rows each)
    const int warpN = wid >> 1;    // 4 warps along N (32 cols each)

    const float* Ab = A + (size_t)blockIdx.y * 128 * 256;
    const float* Bb = B + (size_t)blockIdx.x * 128 * 256;

    // loader mapping: 2 chunks per tensor per thread per stage
    const int lrow0 = tid >> 2;            // 0..63
    const int lc4   = (tid & 3) << 2;      // 0,4,8,12
    const unsigned so0 = (unsigned)((lrow0 * KST + lc4) * 4);
    const unsigned so1 = (unsigned)(((lrow0 + 64) * KST + lc4) * 4);

#define ISSUE_STAGE(s, kt)                                                   \
    do {                                                                     \
        const unsigned sb = sbase + (unsigned)(s) * STAGE_BYTES;             \
        const float* Ak = Ab + (kt) * 16 + lc4;                              \
        const float* Bk = Bb + (kt) * 16 + lc4;                              \
        cp16(sb + so0, Ak + (size_t)lrow0 * 256);                            \
        cp16(sb + so1, Ak + (size_t)(lrow0 + 64) * 256);                     \
        cp16(sb + A_FLOATS * 4 + so0, Bk + (size_t)lrow0 * 256);             \
        cp16(sb + A_FLOATS * 4 + so1, Bk + (size_t)(lrow0 + 64) * 256);      \
        asm volatile("cp.async.commit_group;" ::: "memory");                 \
    } while (0)

    ISSUE_STAGE(0, 0);
    ISSUE_STAGE(1, 1);
    ISSUE_STAGE(2, 2);

    float acc[4][4][4];
#pragma unroll
    for (int mt = 0; mt < 4; mt++)
#pragma unroll
        for (int nt = 0; nt < 4; nt++)
#pragma unroll
            for (int i = 0; i < 4; i++) acc[mt][nt][i] = 0.f;

    for (int kt = 0; kt < 16; kt++) {
        asm volatile("cp.async.wait_group 2;" ::: "memory");
        __syncthreads();
        if (kt + 3 < 16) ISSUE_STAGE((kt + 3) & 3, kt + 3);

        const float* As = smf + (kt & 3) * STAGE_FLOATS;
        const float* Bs = As + A_FLOATS;
#pragma unroll
        for (int k8 = 0; k8 < 2; k8++) {
            unsigned af[4][4], bf[4][2];
#pragma unroll
            for (int mt = 0; mt < 4; mt++) {
                const int base = (warpM * 64 + mt * 16 + g) * KST + k8 * 8 + tg;
                af[mt][0] = f2tf(As[base]);
                af[mt][1] = f2tf(As[base + 8 * KST]);
                af[mt][2] = f2tf(As[base + 4]);
                af[mt][3] = f2tf(As[base + 8 * KST + 4]);
            }
#pragma unroll
            for (int nt = 0; nt < 4; nt++) {
                const int base = (warpN * 32 + nt * 8 + g) * KST + k8 * 8 + tg;
                bf[nt][0] = f2tf(Bs[base]);
                bf[nt][1] = f2tf(Bs[base + 4]);
            }
#pragma unroll
            for (int mt = 0; mt < 4; mt++)
#pragma unroll
                for (int nt = 0; nt < 4; nt++)
                    mma8(acc[mt][nt], af[mt], bf[nt]);
        }
    }
#undef ISSUE_STAGE

#pragma unroll
    for (int mt = 0; mt < 4; mt++) {
        const int r = blockIdx.y * 128 + warpM * 64 + mt * 16 + g;
#pragma unroll
        for (int nt = 0; nt < 4; nt++) {
            const int j = blockIdx.x * 128 + warpN * 32 + nt * 8 + tg * 2;
            const float2 bb = *(const float2*)(bias + j);
            if (REMAP) {
                const int chunk = j >> 5, wi = j & 31;
                float* d0 = C + ((size_t)chunk * MROWS + r) * HDIM + wi;
                float* d1 = C + ((size_t)chunk * MROWS + r + 8) * HDIM + wi;
                *(float2*)d0 = make_float2(f2tff(acc[mt][nt][0] + bb.x),
                                           f2tff(acc[mt][nt][1] + bb.y));
                *(float2*)d1 = make_float2(f2tff(acc[mt][nt][2] + bb.x),
                                           f2tff(acc[mt][nt][3] + bb.y));
            } else {
                *(float2*)(C + (size_t)r * N + j) =
                    make_float2(acc[mt][nt][0] + bb.x, acc[mt][nt][1] + bb.y);
                *(float2*)(C + (size_t)(r + 8) * N + j) =
                    make_float2(acc[mt][nt][2] + bb.x, acc[mt][nt][3] + bb.y);
            }
        }
    }
}

// ---------------------------------------------------------------------------
// Precompute bias+mask tiles: tile t = (h*64 + bmod), 64x64 floats.
// ---------------------------------------------------------------------------
__global__ __launch_bounds__(128)
void prep_bias(const float* __restrict__ mask, const float* __restrict__ rpb,
               float* __restrict__ gb)
{
    const int t = blockIdx.x;
    const int h = t >> 6, bm = t & 63;
    const float* mrow = mask + (size_t)bm * (NTOK * NTOK);
    float* dst = gb + (size_t)t * 4096;
    for (int idx = threadIdx.x; idx < 4096; idx += 128) {
        const int r = idx >> 6, c = idx & 63;
        float v;
        if (c >= 49)      v = -1e30f;
        else if (r >= 49) v = 0.f;
        else {
            const int r1 = r / 7, c1 = r - r1 * 7;
            const int r2 = c / 7, c2 = c - r2 * 7;
            const int bi = (r1 - r2 + 6) * 13 + (c1 - c2 + 6);
            v = mrow[r * 49 + c] + rpb[bi * NHEADS + h];
        }
        dst[idx] = v;
    }
}

// ---------------------------------------------------------------------------
// Window attention with tf32 mma (legacy m16n8k8). Inputs tf32 + head-major.
// ---------------------------------------------------------------------------
#define AT_QS 40
#define AT_VS 56
#define AT_AS 60

__global__ __launch_bounds__(128)
void win_attn_mma(const float* __restrict__ qkv, const float* __restrict__ gbias,
                  float* __restrict__ out)
{
    __shared__ float sq[64 * AT_QS];
    __shared__ float sk[56 * AT_QS];
    __shared__ float sv[32 * AT_VS];
    __shared__ float sa[64 * AT_AS];

    const int b = blockIdx.x >> 3;
    const int h = blockIdx.x & 7;
    const int tid  = threadIdx.x;
    const int lane = tid & 31;
    const int w    = tid >> 5;
    const int g    = lane >> 2;
    const int tg   = lane & 3;
    const float scale = 0.17677669529663687f;

    const float* qb = qkv + ((size_t)h * MROWS + (size_t)b * NTOK) * HDIM;
    const float* kb = qkv + ((size_t)(8 + h) * MROWS + (size_t)b * NTOK) * HDIM;
    const float* vb = qkv + ((size_t)(16 + h) * MROWS + (size_t)b * NTOK) * HDIM;
    for (int idx = tid; idx < NTOK * 8; idx += 128) {
        const int n = idx >> 3, d4 = (idx & 7) << 2;
        const int pbase = (d4 & ~7) + ((d4 >> 2) & 1);
        float4 v;
        v = *(const float4*)(qb + n * HDIM + d4);
        { float* d = &sq[n * AT_QS + pbase]; d[0] = v.x; d[2] = v.y; d[4] = v.z; d[6] = v.w; }
        v = *(const float4*)(kb + n * HDIM + d4);
        { float* d = &sk[n * AT_QS + pbase]; d[0] = v.x; d[2] = v.y; d[4] = v.z; d[6] = v.w; }
        v = *(const float4*)(vb + n * HDIM + d4);
        {
            const int pt = (n & ~7) + ((n & 3) << 1) + ((n >> 2) & 1);
            sv[(d4 + 0) * AT_VS + pt] = v.x;
            sv[(d4 + 1) * AT_VS + pt] = v.y;
            sv[(d4 + 2) * AT_VS + pt] = v.z;
            sv[(d4 + 3) * AT_VS + pt] = v.w;
        }
    }
    const float* bt = gbias + ((size_t)((h << 6) | (b & 63))) * 4096;
#pragma unroll
    for (int j = 0; j < 8; j++) {
        const int idx = tid + j * 128;
        const int r = idx >> 4, c4 = (idx & 15) << 2;
        if (c4 < 56)
            *(float4*)&sa[r * AT_AS + c4] = *(const float4*)(bt + (idx << 2));
    }
    for (int idx = tid; idx < 15 * 32; idx += 128)
        sq[(49 + (idx >> 5)) * AT_QS + (idx & 31)] = 0.f;
    for (int idx = tid; idx < 7 * 32; idx += 128)
        sk[(49 + (idx >> 5)) * AT_QS + (idx & 31)] = 0.f;
    for (int idx = tid; idx < 256; idx += 128) {
        const int d = idx >> 3, j = idx & 7;
        if (j < 7) sv[d * AT_VS + 49 + j] = 0.f;
    }
    __syncthreads();

    const int r0 = w * 16 + g;

    unsigned aq[4][4];
#pragma unroll
    for (int kt = 0; kt < 4; kt++) {
        const float2 lo = *(const float2*)&sq[r0 * AT_QS + kt * 8 + tg * 2];
        const float2 hi = *(const float2*)&sq[(r0 + 8) * AT_QS + kt * 8 + tg * 2];
        aq[kt][0] = __float_as_uint(lo.x);
        aq[kt][1] = __float_as_uint(hi.x);
        aq[kt][2] = __float_as_uint(lo.y);
        aq[kt][3] = __float_as_uint(hi.y);
    }
    float c[7][4];
#pragma unroll
    for (int nt = 0; nt < 7; nt++)
#pragma unroll
        for (int i = 0; i < 4; i++) c[nt][i] = 0.f;

#pragma unroll
    for (int nt = 0; nt < 7; nt++) {
#pragma unroll
        for (int kt = 0; kt < 4; kt++) {
            const float2 bv = *(const float2*)&sk[(nt * 8 + g) * AT_QS + kt * 8 + tg * 2];
            unsigned bb[2] = { __float_as_uint(bv.x), __float_as_uint(bv.y) };
            mma8(c[nt], aq[kt], bb);
        }
    }

    float mx0 = -1e30f, mx1 = -1e30f;
#pragma unroll
    for (int nt = 0; nt < 7; nt++) {
        const float2 b0 = *(const float2*)&sa[r0 * AT_AS + nt * 8 + tg * 2];
        const float2 b1 = *(const float2*)&sa[(r0 + 8) * AT_AS + nt * 8 + tg * 2];
        c[nt][0] = fmaf(c[nt][0], scale, b0.x);
        c[nt][1] = fmaf(c[nt][1], scale, b0.y);
        c[nt][2] = fmaf(c[nt][2], scale, b1.x);
        c[nt][3] = fmaf(c[nt][3], scale, b1.y);
        mx0 = fmaxf(mx0, fmaxf(c[nt][0], c[nt][1]));
        mx1 = fmaxf(mx1, fmaxf(c[nt][2], c[nt][3]));
    }
    mx0 = fmaxf(mx0, __shfl_xor_sync(0xffffffffu, mx0, 1));
    mx0 = fmaxf(mx0, __shfl_xor_sync(0xffffffffu, mx0, 2));
    mx1 = fmaxf(mx1, __shfl_xor_sync(0xffffffffu, mx1, 1));
    mx1 = fmaxf(mx1, __shfl_xor_sync(0xffffffffu, mx1, 2));

    float s0 = 0.f, s1 = 0.f;
#pragma unroll
    for (int nt = 0; nt < 7; nt++) {
        c[nt][0] = __expf(c[nt][0] - mx0);
        c[nt][1] = __expf(c[nt][1] - mx0);
        c[nt][2] = __expf(c[nt][2] - mx1);
        c[nt][3] = __expf(c[nt][3] - mx1);
        s0 += c[nt][0] + c[nt][1];
        s1 += c[nt][2] + c[nt][3];
    }
    s0 += __shfl_xor_sync(0xffffffffu, s0, 1);
    s0 += __shfl_xor_sync(0xffffffffu, s0, 2);
    s1 += __shfl_xor_sync(0xffffffffu, s1, 1);
    s1 += __shfl_xor_sync(0xffffffffu, s1, 2);
    const float i0 = 1.f / s0, i1 = 1.f / s1;

    __syncwarp();
#pragma unroll
    for (int nt = 0; nt < 7; nt++) {
        float2 p0 = make_float2(f2tff(c[nt][0] * i0), f2tff(c[nt][1] * i0));
        float2 p1 = make_float2(f2tff(c[nt][2] * i1), f2tff(c[nt][3] * i1));
        *(float2*)&sa[r0 * AT_AS + nt * 8 + tg * 2]       = p0;
        *(float2*)&sa[(r0 + 8) * AT_AS + nt * 8 + tg * 2] = p1;
    }
    __syncwarp();

    float cv[4][4];
#pragma unroll
    for (int nt = 0; nt < 4; nt++)
#pragma unroll
        for (int i = 0; i < 4; i++) cv[nt][i] = 0.f;

#pragma unroll
    for (int kt = 0; kt < 7; kt++) {
        unsigned ap[4];
        ap[0] = __float_as_uint(sa[r0 * AT_AS + kt * 8 + tg]);
        ap[1] = __float_as_uint(sa[(r0 + 8) * AT_AS + kt * 8 + tg]);
        ap[2] = __float_as_uint(sa[r0 * AT_AS + kt * 8 + tg + 4]);
        ap[3] = __float_as_uint(sa[(r0 + 8) * AT_AS + kt * 8 + tg + 4]);
#pragma unroll
        for (int nt = 0; nt < 4; nt++) {
            const float2 bv = *(const float2*)&sv[(nt * 8 + g) * AT_VS + kt * 8 + tg * 2];
            unsigned bb[2] = { __float_as_uint(bv.x), __float_as_uint(bv.y) };
            mma8(cv[nt], ap, bb);
        }
    }

    float* ob = out + (size_t)b * NTOK * CDIM + h * HDIM;
    if (r0 < NTOK) {
#pragma unroll
        for (int nt = 0; nt < 4; nt++)
            *(float2*)&ob[(size_t)r0 * CDIM + nt * 8 + tg * 2] =
                make_float2(cv[nt][0], cv[nt][1]);
    }
    if (r0 + 8 < NTOK) {
#pragma unroll
        for (int nt = 0; nt < 4; nt++)
            *(float2*)&ob[(size_t)(r0 + 8) * CDIM + nt * 8 + tg * 2] =
                make_float2(cv[nt][2], cv[nt][3]);
    }
}

// ---------------------------------------------------------------------------
extern "C" void kernel_launch(void* const* d_in, const int* in_sizes, int n_in,
                              void* d_out, int out_size)
{
    const float* x      = (const float*)d_in[0];
    const float* mask   = (const float*)d_in[1];
    const float* qkv_w  = (const float*)d_in[2];
    const float* qkv_b  = (const float*)d_in[3];
    const float* proj_w = (const float*)d_in[4];
    const float* proj_b = (const float*)d_in[5];
    const float* rpb    = (const float*)d_in[6];
    float* out = (float*)d_out;

    void *qkv_ptr = nullptr, *att_ptr = nullptr, *bias_ptr = nullptr;
    cudaGetSymbolAddress(&qkv_ptr, g_qkv);
    cudaGetSymbolAddress(&att_ptr, g_att);
    cudaGetSymbolAddress(&bias_ptr, g_bias);
    float* qkv_s  = (float*)qkv_ptr;
    float* att_s  = (float*)att_ptr;
    float* bias_s = (float*)bias_ptr;

    cudaFuncSetAttribute(gemm_ca<1>, cudaFuncAttributeMaxDynamicSharedMemorySize, GEMM_SMEM);
    cudaFuncSetAttribute(gemm_ca<0>, cudaFuncAttributeMaxDynamicSharedMemorySize, GEMM_SMEM);

    // 0) precompute bias+mask tiles
    prep_bias<<<512, 128>>>(mask, rpb, bias_s);
    // 1) QKV GEMM -> head-major tf32-rounded scratch
    gemm_ca<1><<<dim3(6, MROWS / 128), 256, GEMM_SMEM>>>(x, qkv_w, qkv_b, qkv_s, 3 * CDIM);
    // 2) windowed attention (tf32 mma) -> g_att
    win_attn_mma<<<BWIN * NHEADS, 128>>>(qkv_s, bias_s, att_s);
    // 3) proj GEMM -> out (row-major f32)
    gemm_ca<0><<<dim3(2, MROWS / 128), 256, GEMM_SMEM>>>(att_s, proj_w, proj_b, out, CDIM);
}

// round 14
// speedup vs baseline: 1.7413x; 1.0292x over previous
#include <cuda_runtime.h>

#define NTOK   49
#define NHEADS 8
#define HDIM   32
#define CDIM   256
#define BWIN   4096
#define MROWS  (BWIN * NTOK)   /* 200704 */
#define NWIN   64

// Scratch (device-global arrays: allocation-free per harness rules)
__device__ float g_qkv[(size_t)MROWS * 3 * CDIM];   // head-major chunks, tf32
__device__ float g_att[(size_t)MROWS * CDIM];       // (M,256) row-major, tf32-rounded
__device__ float g_bias[512 * 64 * 64];             // bias+mask tiles
__device__ float g_w1[768 * 256];                   // tf32-rounded qkv_w
__device__ float g_w2[256 * 256];                   // tf32-rounded proj_w

__device__ __forceinline__ unsigned f2tf(float x) {
    unsigned u;
    asm("cvt.rna.tf32.f32 %0, %1;" : "=r"(u) : "f"(x));
    return u;
}
__device__ __forceinline__ float f2tff(float x) {
    return __uint_as_float(f2tf(x));
}
__device__ __forceinline__ unsigned smem_u32(const void* p) {
    unsigned a;
    asm("{ .reg .u64 t; cvta.to.shared.u64 t, %1; cvt.u32.u64 %0, t; }" : "=r"(a) : "l"(p));
    return a;
}
__device__ __forceinline__ void cp16(unsigned dst, const float* src) {
    asm volatile("cp.async.cg.shared.global [%0], [%1], 16;" :: "r"(dst), "l"(src));
}
__device__ __forceinline__ void mma8(float* c, const unsigned* a, const unsigned* b) {
    asm volatile(
        "mma.sync.aligned.m16n8k8.row.col.f32.tf32.tf32.f32 "
        "{%0,%1,%2,%3}, {%4,%5,%6,%7}, {%8,%9}, {%0,%1,%2,%3};\n"
        : "+f"(c[0]), "+f"(c[1]), "+f"(c[2]), "+f"(c[3])
        : "r"(a[0]), "r"(a[1]), "r"(a[2]), "r"(a[3]), "r"(b[0]), "r"(b[1]));
}

// ---------------------------------------------------------------------------
// C[M,N] = A[M,256] @ B[N,256]^T + bias[N]   (tf32 mma)
// Block 128x128, 8 warps (2M x 4N), warp tile 64x32, 2 CTAs/SM.
// 4-stage cp.async pipeline + cross-iteration register fragment double-buffer.
// RACE-FIX vs prior attempt: every fragment load of stage s happens only after
// (own wait_group for s) AND a __syncthreads() — cp.async completion is
// per-thread; cross-thread smem visibility requires the barrier.
// ---------------------------------------------------------------------------
#define KST 20
#define A_FLOATS (128 * KST)
#define STAGE_FLOATS (2 * A_FLOATS)
#define STAGE_BYTES (STAGE_FLOATS * 4)
#define NSTAGE 4
#define GEMM_SMEM (NSTAGE * STAGE_BYTES) /* 81920 B */

template <int CVTA>
__device__ __forceinline__ void load_frag(const float* __restrict__ stg,
                                          int warpM, int warpN, int g, int tg, int k8,
                                          unsigned af[4][4], unsigned bf[4][2])
{
    const float* As = stg;
    const float* Bs = stg + A_FLOATS;
#pragma unroll
    for (int mt = 0; mt < 4; mt++) {
        const int base = (warpM * 64 + mt * 16 + g) * KST + k8 * 8 + tg;
        if (CVTA) {
            af[mt][0] = f2tf(As[base]);
            af[mt][1] = f2tf(As[base + 8 * KST]);
            af[mt][2] = f2tf(As[base + 4]);
            af[mt][3] = f2tf(As[base + 8 * KST + 4]);
        } else {
            af[mt][0] = __float_as_uint(As[base]);
            af[mt][1] = __float_as_uint(As[base + 8 * KST]);
            af[mt][2] = __float_as_uint(As[base + 4]);
            af[mt][3] = __float_as_uint(As[base + 8 * KST + 4]);
        }
    }
#pragma unroll
    for (int nt = 0; nt < 4; nt++) {
        const int base = (warpN * 32 + nt * 8 + g) * KST + k8 * 8 + tg;
        bf[nt][0] = __float_as_uint(Bs[base]);
        bf[nt][1] = __float_as_uint(Bs[base + 4]);
    }
}

template <int REMAP, int CVTA>
__global__ __launch_bounds__(256, 2)
void gemm_ca(const float* __restrict__ A, const float* __restrict__ B,
             const float* __restrict__ bias, float* __restrict__ C, int N)
{
    extern __shared__ float smf[];
    const unsigned sbase = smem_u32(smf);

    const int tid   = threadIdx.x;
    const int lane  = tid & 31;
    const int wid   = tid >> 5;
    const int g     = lane >> 2;
    const int tg    = lane & 3;
    const int warpM = wid & 1;
    const int warpN = wid >> 1;

    const float* Ab = A + (size_t)blockIdx.y * 128 * 256;
    const float* Bb = B + (size_t)blockIdx.x * 128 * 256;

    const int lrow0 = tid >> 2;
    const int lc4   = (tid & 3) << 2;
    const unsigned so0 = (unsigned)((lrow0 * KST + lc4) * 4);
    const unsigned so1 = (unsigned)(((lrow0 + 64) * KST + lc4) * 4);

#define ISSUE_STAGE(s, kt)                                                   \
    do {                                                                     \
        const unsigned sb = sbase + (unsigned)(s) * STAGE_BYTES;             \
        const float* Ak = Ab + (kt) * 16 + lc4;                              \
        const float* Bk = Bb + (kt) * 16 + lc4;                              \
        cp16(sb + so0, Ak + (size_t)lrow0 * 256);                            \
        cp16(sb + so1, Ak + (size_t)(lrow0 + 64) * 256);                     \
        cp16(sb + A_FLOATS * 4 + so0, Bk + (size_t)lrow0 * 256);             \
        cp16(sb + A_FLOATS * 4 + so1, Bk + (size_t)(lrow0 + 64) * 256);      \
        asm volatile("cp.async.commit_group;" ::: "memory");                 \
    } while (0)

    ISSUE_STAGE(0, 0);
    ISSUE_STAGE(1, 1);
    ISSUE_STAGE(2, 2);
    ISSUE_STAGE(3, 3);

    float acc[4][4][4];
#pragma unroll
    for (int mt = 0; mt < 4; mt++)
#pragma unroll
        for (int nt = 0; nt < 4; nt++)
#pragma unroll
            for (int i = 0; i < 4; i++) acc[mt][nt][i] = 0.f;

    unsigned af0[4][4], bf0[4][2], af1[4][4], bf1[4][2];

    // stage 0 ready for ALL threads: own-wait + barrier
    asm volatile("cp.async.wait_group 3;" ::: "memory");
    __syncthreads();
    load_frag<CVTA>(smf, warpM, warpN, g, tg, 0, af0, bf0);

    for (int kt = 0; kt < 16; kt++) {
        // stage kt fully visible (sync above / mid-loop sync of kt-1)
        load_frag<CVTA>(smf + (kt & 3) * STAGE_FLOATS, warpM, warpN, g, tg, 1, af1, bf1);

#pragma unroll
        for (int mt = 0; mt < 4; mt++)
#pragma unroll
            for (int nt = 0; nt < 4; nt++)
                mma8(acc[mt][nt], af0[mt], bf0[nt]);

        if (kt + 1 < 16) {
            // retire stage kt+1 (own), then barrier => visible to all threads.
            if (kt <= 12)      asm volatile("cp.async.wait_group 2;" ::: "memory");
            else if (kt == 13) asm volatile("cp.async.wait_group 1;" ::: "memory");
            else               asm volatile("cp.async.wait_group 0;" ::: "memory");
            __syncthreads();
            // slot kt&3: all reads (af1 above, by every thread) precede the sync
            if (kt + 4 < 16) ISSUE_STAGE(kt & 3, kt + 4);
            load_frag<CVTA>(smf + ((kt + 1) & 3) * STAGE_FLOATS, warpM, warpN, g, tg, 0, af0, bf0);
        }

#pragma unroll
        for (int mt = 0; mt < 4; mt++)
#pragma unroll
            for (int nt = 0; nt < 4; nt++)
                mma8(acc[mt][nt], af1[mt], bf1[nt]);
    }
#undef ISSUE_STAGE

#pragma unroll
    for (int mt = 0; mt < 4; mt++) {
        const int r = blockIdx.y * 128 + warpM * 64 + mt * 16 + g;
#pragma unroll
        for (int nt = 0; nt < 4; nt++) {
            const int j = blockIdx.x * 128 + warpN * 32 + nt * 8 + tg * 2;
            const float2 bb = *(const float2*)(bias + j);
            if (REMAP) {
                const int chunk = j >> 5, wi = j & 31;
                float* d0 = C + ((size_t)chunk * MROWS + r) * HDIM + wi;
                float* d1 = C + ((size_t)chunk * MROWS + r + 8) * HDIM + wi;
                *(float2*)d0 = make_float2(f2tff(acc[mt][nt][0] + bb.x),
                                           f2tff(acc[mt][nt][1] + bb.y));
                *(float2*)d1 = make_float2(f2tff(acc[mt][nt][2] + bb.x),
                                           f2tff(acc[mt][nt][3] + bb.y));
            } else {
                *(float2*)(C + (size_t)r * N + j) =
                    make_float2(acc[mt][nt][0] + bb.x, acc[mt][nt][1] + bb.y);
                *(float2*)(C + (size_t)(r + 8) * N + j) =
                    make_float2(acc[mt][nt][2] + bb.x, acc[mt][nt][3] + bb.y);
            }
        }
    }
}

// ---------------------------------------------------------------------------
// Prep: round weights to tf32 tables.
// ---------------------------------------------------------------------------
__global__ __launch_bounds__(256)
void prep_w(const float* __restrict__ qkv_w, const float* __restrict__ proj_w,
            float* __restrict__ w1, float* __restrict__ w2)
{
    const int i = blockIdx.x * 256 + threadIdx.x;   // float4 index
    if (i < 49152) {
        float4 v = ((const float4*)qkv_w)[i];
        ((float4*)w1)[i] = make_float4(f2tff(v.x), f2tff(v.y), f2tff(v.z), f2tff(v.w));
    }
    if (i < 16384) {
        float4 v = ((const float4*)proj_w)[i];
        ((float4*)w2)[i] = make_float4(f2tff(v.x), f2tff(v.y), f2tff(v.z), f2tff(v.w));
    }
}

// ---------------------------------------------------------------------------
// Prep: bias+mask tiles, tile t = (h*64 + bmod), 64x64 floats.
// ---------------------------------------------------------------------------
__global__ __launch_bounds__(128)
void prep_bias(const float* __restrict__ mask, const float* __restrict__ rpb,
               float* __restrict__ gb)
{
    const int t = blockIdx.x;
    const int h = t >> 6, bm = t & 63;
    const float* mrow = mask + (size_t)bm * (NTOK * NTOK);
    float* dst = gb + (size_t)t * 4096;
    for (int idx = threadIdx.x; idx < 4096; idx += 128) {
        const int r = idx >> 6, c = idx & 63;
        float v;
        if (c >= 49)      v = -1e30f;
        else if (r >= 49) v = 0.f;
        else {
            const int r1 = r / 7, c1 = r - r1 * 7;
            const int r2 = c / 7, c2 = c - r2 * 7;
            const int bi = (r1 - r2 + 6) * 13 + (c1 - c2 + 6);
            v = mrow[r * 49 + c] + rpb[bi * NHEADS + h];
        }
        dst[idx] = v;
    }
}

// ---------------------------------------------------------------------------
// Window attention with tf32 mma (legacy m16n8k8). Inputs tf32 + head-major.
// Output written tf32-rounded (proj consumes without cvt).
// ---------------------------------------------------------------------------
#define AT_QS 40
#define AT_VS 56
#define AT_AS 60

__global__ __launch_bounds__(128)
void win_attn_mma(const float* __restrict__ qkv, const float* __restrict__ gbias,
                  float* __restrict__ out)
{
    __shared__ float sq[64 * AT_QS];
    __shared__ float sk[56 * AT_QS];
    __shared__ float sv[32 * AT_VS];
    __shared__ float sa[64 * AT_AS];

    const int b = blockIdx.x >> 3;
    const int h = blockIdx.x & 7;
    const int tid  = threadIdx.x;
    const int lane = tid & 31;
    const int w    = tid >> 5;
    const int g    = lane >> 2;
    const int tg   = lane & 3;
    const float scale = 0.17677669529663687f;

    const float* qb = qkv + ((size_t)h * MROWS + (size_t)b * NTOK) * HDIM;
    const float* kb = qkv + ((size_t)(8 + h) * MROWS + (size_t)b * NTOK) * HDIM;
    const float* vb = qkv + ((size_t)(16 + h) * MROWS + (size_t)b * NTOK) * HDIM;
    for (int idx = tid; idx < NTOK * 8; idx += 128) {
        const int n = idx >> 3, d4 = (idx & 7) << 2;
        const int pbase = (d4 & ~7) + ((d4 >> 2) & 1);
        float4 v;
        v = *(const float4*)(qb + n * HDIM + d4);
        { float* d = &sq[n * AT_QS + pbase]; d[0] = v.x; d[2] = v.y; d[4] = v.z; d[6] = v.w; }
        v = *(const float4*)(kb + n * HDIM + d4);
        { float* d = &sk[n * AT_QS + pbase]; d[0] = v.x; d[2] = v.y; d[4] = v.z; d[6] = v.w; }
        v = *(const float4*)(vb + n * HDIM + d4);
        {
            const int pt = (n & ~7) + ((n & 3) << 1) + ((n >> 2) & 1);
            sv[(d4 + 0) * AT_VS + pt] = v.x;
            sv[(d4 + 1) * AT_VS + pt] = v.y;
            sv[(d4 + 2) * AT_VS + pt] = v.z;
            sv[(d4 + 3) * AT_VS + pt] = v.w;
        }
    }
    const float* bt = gbias + ((size_t)((h << 6) | (b & 63))) * 4096;
#pragma unroll
    for (int j = 0; j < 8; j++) {
        const int idx = tid + j * 128;
        const int r = idx >> 4, c4 = (idx & 15) << 2;
        if (c4 < 56)
            *(float4*)&sa[r * AT_AS + c4] = *(const float4*)(bt + (idx << 2));
    }
    for (int idx = tid; idx < 15 * 32; idx += 128)
        sq[(49 + (idx >> 5)) * AT_QS + (idx & 31)] = 0.f;
    for (int idx = tid; idx < 7 * 32; idx += 128)
        sk[(49 + (idx >> 5)) * AT_QS + (idx & 31)] = 0.f;
    for (int idx = tid; idx < 256; idx += 128) {
        const int d = idx >> 3, j = idx & 7;
        if (j < 7) sv[d * AT_VS + 49 + j] = 0.f;
    }
    __syncthreads();

    const int r0 = w * 16 + g;

    unsigned aq[4][4];
#pragma unroll
    for (int kt = 0; kt < 4; kt++) {
        const float2 lo = *(const float2*)&sq[r0 * AT_QS + kt * 8 + tg * 2];
        const float2 hi = *(const float2*)&sq[(r0 + 8) * AT_QS + kt * 8 + tg * 2];
        aq[kt][0] = __float_as_uint(lo.x);
        aq[kt][1] = __float_as_uint(hi.x);
        aq[kt][2] = __float_as_uint(lo.y);
        aq[kt][3] = __float_as_uint(hi.y);
    }
    float c[7][4];
#pragma unroll
    for (int nt = 0; nt < 7; nt++)
#pragma unroll
        for (int i = 0; i < 4; i++) c[nt][i] = 0.f;

#pragma unroll
    for (int nt = 0; nt < 7; nt++) {
#pragma unroll
        for (int kt = 0; kt < 4; kt++) {
            const float2 bv = *(const float2*)&sk[(nt * 8 + g) * AT_QS + kt * 8 + tg * 2];
            unsigned bb[2] = { __float_as_uint(bv.x), __float_as_uint(bv.y) };
            mma8(c[nt], aq[kt], bb);
        }
    }

    float mx0 = -1e30f, mx1 = -1e30f;
#pragma unroll
    for (int nt = 0; nt < 7; nt++) {
        const float2 b0 = *(const float2*)&sa[r0 * AT_AS + nt * 8 + tg * 2];
        const float2 b1 = *(const float2*)&sa[(r0 + 8) * AT_AS + nt * 8 + tg * 2];
        c[nt][0] = fmaf(c[nt][0], scale, b0.x);
        c[nt][1] = fmaf(c[nt][1], scale, b0.y);
        c[nt][2] = fmaf(c[nt][2], scale, b1.x);
        c[nt][3] = fmaf(c[nt][3], scale, b1.y);
        mx0 = fmaxf(mx0, fmaxf(c[nt][0], c[nt][1]));
        mx1 = fmaxf(mx1, fmaxf(c[nt][2], c[nt][3]));
    }
    mx0 = fmaxf(mx0, __shfl_xor_sync(0xffffffffu, mx0, 1));
    mx0 = fmaxf(mx0, __shfl_xor_sync(0xffffffffu, mx0, 2));
    mx1 = fmaxf(mx1, __shfl_xor_sync(0xffffffffu, mx1, 1));
    mx1 = fmaxf(mx1, __shfl_xor_sync(0xffffffffu, mx1, 2));

    float s0 = 0.f, s1 = 0.f;
#pragma unroll
    for (int nt = 0; nt < 7; nt++) {
        c[nt][0] = __expf(c[nt][0] - mx0);
        c[nt][1] = __expf(c[nt][1] - mx0);
        c[nt][2] = __expf(c[nt][2] - mx1);
        c[nt][3] = __expf(c[nt][3] - mx1);
        s0 += c[nt][0] + c[nt][1];
        s1 += c[nt][2] + c[nt][3];
    }
    s0 += __shfl_xor_sync(0xffffffffu, s0, 1);
    s0 += __shfl_xor_sync(0xffffffffu, s0, 2);
    s1 += __shfl_xor_sync(0xffffffffu, s1, 1);
    s1 += __shfl_xor_sync(0xffffffffu, s1, 2);
    const float i0 = 1.f / s0, i1 = 1.f / s1;

    __syncwarp();
#pragma unroll
    for (int nt = 0; nt < 7; nt++) {
        float2 p0 = make_float2(f2tff(c[nt][0] * i0), f2tff(c[nt][1] * i0));
        float2 p1 = make_float2(f2tff(c[nt][2] * i1), f2tff(c[nt][3] * i1));
        *(float2*)&sa[r0 * AT_AS + nt * 8 + tg * 2]       = p0;
        *(float2*)&sa[(r0 + 8) * AT_AS + nt * 8 + tg * 2] = p1;
    }
    __syncwarp();

    float cv[4][4];
#pragma unroll
    for (int nt = 0; nt < 4; nt++)
#pragma unroll
        for (int i = 0; i < 4; i++) cv[nt][i] = 0.f;

#pragma unroll
    for (int kt = 0; kt < 7; kt++) {
        unsigned ap[4];
        ap[0] = __float_as_uint(sa[r0 * AT_AS + kt * 8 + tg]);
        ap[1] = __float_as_uint(sa[(r0 + 8) * AT_AS + kt * 8 + tg]);
        ap[2] = __float_as_uint(sa[r0 * AT_AS + kt * 8 + tg + 4]);
        ap[3] = __float_as_uint(sa[(r0 + 8) * AT_AS + kt * 8 + tg + 4]);
#pragma unroll
        for (int nt = 0; nt < 4; nt++) {
            const float2 bv = *(const float2*)&sv[(nt * 8 + g) * AT_VS + kt * 8 + tg * 2];
            unsigned bb[2] = { __float_as_uint(bv.x), __float_as_uint(bv.y) };
            mma8(cv[nt], ap, bb);
        }
    }

    // store tf32-rounded so proj can consume without cvt
    float* ob = out + (size_t)b * NTOK * CDIM + h * HDIM;
    if (r0 < NTOK) {
#pragma unroll
        for (int nt = 0; nt < 4; nt++)
            *(float2*)&ob[(size_t)r0 * CDIM + nt * 8 + tg * 2] =
                make_float2(f2tff(cv[nt][0]), f2tff(cv[nt][1]));
    }
    if (r0 + 8 < NTOK) {
#pragma unroll
        for (int nt = 0; nt < 4; nt++)
            *(float2*)&ob[(size_t)(r0 + 8) * CDIM + nt * 8 + tg * 2] =
                make_float2(f2tff(cv[nt][2]), f2tff(cv[nt][3]));
    }
}

// ---------------------------------------------------------------------------
extern "C" void kernel_launch(void* const* d_in, const int* in_sizes, int n_in,
                              void* d_out, int out_size)
{
    const float* x      = (const float*)d_in[0];
    const float* mask   = (const float*)d_in[1];
    const float* qkv_w  = (const float*)d_in[2];
    const float* qkv_b  = (const float*)d_in[3];
    const float* proj_w = (const float*)d_in[4];
    const float* proj_b = (const float*)d_in[5];
    const float* rpb    = (const float*)d_in[6];
    float* out = (float*)d_out;

    void *qkv_ptr = nullptr, *att_ptr = nullptr, *bias_ptr = nullptr;
    void *w1_ptr = nullptr, *w2_ptr = nullptr;
    cudaGetSymbolAddress(&qkv_ptr, g_qkv);
    cudaGetSymbolAddress(&att_ptr, g_att);
    cudaGetSymbolAddress(&bias_ptr, g_bias);
    cudaGetSymbolAddress(&w1_ptr, g_w1);
    cudaGetSymbolAddress(&w2_ptr, g_w2);
    float* qkv_s  = (float*)qkv_ptr;
    float* att_s  = (float*)att_ptr;
    float* bias_s = (float*)bias_ptr;
    float* w1_s   = (float*)w1_ptr;
    float* w2_s   = (float*)w2_ptr;

    cudaFuncSetAttribute(gemm_ca<1, 1>, cudaFuncAttributeMaxDynamicSharedMemorySize, GEMM_SMEM);
    cudaFuncSetAttribute(gemm_ca<0, 0>, cudaFuncAttributeMaxDynamicSharedMemorySize, GEMM_SMEM);

    // 0) prep: weight tf32 tables + bias/mask tiles
    prep_w<<<192, 256>>>(qkv_w, proj_w, w1_s, w2_s);
    prep_bias<<<512, 128>>>(mask, rpb, bias_s);
    // 1) QKV GEMM (A cvt, B pre-rounded) -> head-major tf32 scratch
    gemm_ca<1, 1><<<dim3(6, MROWS / 128), 256, GEMM_SMEM>>>(x, w1_s, qkv_b, qkv_s, 3 * CDIM);
    // 2) windowed attention -> g_att (tf32-rounded)
    win_attn_mma<<<BWIN * NHEADS, 128>>>(qkv_s, bias_s, att_s);
    // 3) proj GEMM (A and B pre-rounded, no cvt) -> out
    gemm_ca<0, 0><<<dim3(2, MROWS / 128), 256, GEMM_SMEM>>>(att_s, w2_s, proj_b, out, CDIM);
}